// round 2
// baseline (speedup 1.0000x reference)
#include <cuda_runtime.h>
#include <cuda_bf16.h>
#include <mma.h>
#include <cstddef>

using namespace nvcuda;

#define NN 50000
#define EE 600000
#define GG 512
#define MM 2048
#define DD 128
#define FFN 256
#define LL 3
#define BN_EPS 1e-5f

// ---------------- scratch (device globals; no allocation allowed) ----------------
__device__ float g_bufA[NN * DD];
__device__ float g_bufB[NN * DD];
__device__ float g_bufC[NN * DD];
__device__ float g_bufR[NN * DD];
__device__ float g_norm_src[NN];
__device__ float g_norm_dst[NN];
__device__ float g_stats[2 * DD];
__device__ float g_gsum[GG * DD];
__device__ float g_gcnt[GG];
__device__ float g_msum[(MM + 1) * DD];
__device__ float g_mcnt[MM + 1];
__device__ float g_headin[(GG + MM) * DD];
__device__ float g_head1[(GG + MM) * FFN];
__device__ float g_head2[(GG + MM) * FFN];

// ---------------- degree / norm ----------------
__global__ void k_degrees(const int* __restrict__ src, const int* __restrict__ dst) {
    int e = blockIdx.x * blockDim.x + threadIdx.x;
    if (e < EE) {
        atomicAdd(&g_norm_src[src[e]], 1.0f);
        atomicAdd(&g_norm_dst[dst[e]], 1.0f);
    }
}

__global__ void k_norms() {
    int i = blockIdx.x * blockDim.x + threadIdx.x;
    if (i < NN) {
        g_norm_src[i] = rsqrtf(fmaxf(g_norm_src[i], 1.0f));
        g_norm_dst[i] = rsqrtf(fmaxf(g_norm_dst[i], 1.0f));
    }
}

// ---------------- fused dual GEMM (TF32 tensor cores) ----------------
// Y1 = rowscale .* (X @ W1)              (the GCN hw branch; rowscale commutes out)
// Y2 = relu(X @ W2 + b2)                 (the residual branch)
// X: [nrows,128], W1/W2: [128,128]. Block = 256 thr, 64 rows. K=128 single chunk.
__global__ void k_dualgemm(const float* __restrict__ X,
                           const float* __restrict__ W1,
                           const float* __restrict__ W2,
                           const float* __restrict__ b2,
                           const float* __restrict__ rs,
                           float* __restrict__ Y1, float* __restrict__ Y2,
                           int nrows) {
    extern __shared__ float sm[];
    float* Xs  = sm;                 // 64*128
    float* W1s = sm + 64 * 128;      // 128*128
    float* W2s = W1s + 128 * 128;    // 128*128
    const int tid = threadIdx.x;
    const int r0 = blockIdx.x * 64;

#pragma unroll
    for (int i = 0; i < 16; i++) {
        int f = tid + 256 * i;       // 4096 float4
        ((float4*)W1s)[f] = ((const float4*)W1)[f];
        ((float4*)W2s)[f] = ((const float4*)W2)[f];
    }
#pragma unroll
    for (int i = 0; i < 8; i++) {
        int f = tid + 256 * i;       // 2048 float4
        int row = r0 + (f >> 5);
        float4 v = make_float4(0.f, 0.f, 0.f, 0.f);
        if (row < nrows) v = ((const float4*)(X + (size_t)row * DD))[f & 31];
        ((float4*)Xs)[f] = v;
    }
    __syncthreads();

    const int w = tid >> 5;
    const int wr = (w & 1) * 32;     // warp row offset within 64
    const int wc = (w >> 1) * 32;    // warp col offset within 128

    wmma::fragment<wmma::accumulator, 16, 16, 8, float> acc1[2][2], acc2[2][2];
#pragma unroll
    for (int i = 0; i < 2; i++)
#pragma unroll
        for (int j = 0; j < 2; j++) {
            wmma::fill_fragment(acc1[i][j], 0.f);
            wmma::fill_fragment(acc2[i][j], 0.f);
        }

#pragma unroll
    for (int k = 0; k < DD; k += 8) {
        wmma::fragment<wmma::matrix_a, 16, 16, 8, wmma::precision::tf32, wmma::row_major> a[2];
        wmma::fragment<wmma::matrix_b, 16, 16, 8, wmma::precision::tf32, wmma::row_major> bf1[2], bf2[2];
#pragma unroll
        for (int i = 0; i < 2; i++) {
            wmma::load_matrix_sync(a[i], Xs + (wr + 16 * i) * DD + k, DD);
#pragma unroll
            for (int t = 0; t < a[i].num_elements; t++) a[i].x[t] = wmma::__float_to_tf32(a[i].x[t]);
            wmma::load_matrix_sync(bf1[i], W1s + k * DD + wc + 16 * i, DD);
#pragma unroll
            for (int t = 0; t < bf1[i].num_elements; t++) bf1[i].x[t] = wmma::__float_to_tf32(bf1[i].x[t]);
            wmma::load_matrix_sync(bf2[i], W2s + k * DD + wc + 16 * i, DD);
#pragma unroll
            for (int t = 0; t < bf2[i].num_elements; t++) bf2[i].x[t] = wmma::__float_to_tf32(bf2[i].x[t]);
        }
#pragma unroll
        for (int i = 0; i < 2; i++)
#pragma unroll
            for (int j = 0; j < 2; j++) {
                wmma::mma_sync(acc1[i][j], a[i], bf1[j], acc1[i][j]);
                wmma::mma_sync(acc2[i][j], a[i], bf2[j], acc2[i][j]);
            }
    }
    __syncthreads();   // everyone done reading smem

    float* stage = sm;  // reuse first 64*128 floats
    // ---- Y1 epilogue: rowscale ----
#pragma unroll
    for (int i = 0; i < 2; i++)
#pragma unroll
        for (int j = 0; j < 2; j++)
            wmma::store_matrix_sync(stage + (wr + 16 * i) * DD + wc + 16 * j, acc1[i][j], DD, wmma::mem_row_major);
    __syncthreads();
#pragma unroll
    for (int i = 0; i < 8; i++) {
        int f = tid + 256 * i;
        int row = r0 + (f >> 5);
        if (row < nrows) {
            float s = rs[row];
            float4 v = ((float4*)stage)[f];
            v.x *= s; v.y *= s; v.z *= s; v.w *= s;
            ((float4*)(Y1 + (size_t)row * DD))[f & 31] = v;
        }
    }
    __syncthreads();
    // ---- Y2 epilogue: bias + relu ----
#pragma unroll
    for (int i = 0; i < 2; i++)
#pragma unroll
        for (int j = 0; j < 2; j++)
            wmma::store_matrix_sync(stage + (wr + 16 * i) * DD + wc + 16 * j, acc2[i][j], DD, wmma::mem_row_major);
    __syncthreads();
#pragma unroll
    for (int i = 0; i < 8; i++) {
        int f = tid + 256 * i;
        int row = r0 + (f >> 5);
        if (row < nrows) {
            float4 b4 = ((const float4*)b2)[f & 31];
            float4 v = ((float4*)stage)[f];
            v.x = fmaxf(v.x + b4.x, 0.f);
            v.y = fmaxf(v.y + b4.y, 0.f);
            v.z = fmaxf(v.z + b4.z, 0.f);
            v.w = fmaxf(v.w + b4.w, 0.f);
            ((float4*)(Y2 + (size_t)row * DD))[f & 31] = v;
        }
    }
}

// ---------------- fp32 tiled GEMM (head MLP; small) ----------------
__global__ void k_gemm(const float* __restrict__ X, const float* __restrict__ W,
                       const float* __restrict__ bias, const float* __restrict__ rowscale,
                       float* __restrict__ Y, int nrows, int K, int ncols, int do_relu) {
    extern __shared__ float sm[];
    float* Ws = sm;               // 128*128
    float* Xs = sm + 128 * 128;   // 64*128
    const int tid = threadIdx.x;
    const int tx = tid & 31;
    const int ty = tid >> 5;
    const int r0 = blockIdx.x * 64;
    const int c0 = blockIdx.y * 128;

    float4 acc[8];
#pragma unroll
    for (int m = 0; m < 8; m++) acc[m] = make_float4(0.f, 0.f, 0.f, 0.f);

    for (int kb = 0; kb < K; kb += 128) {
#pragma unroll
        for (int i = 0; i < 16; i++) {
            int f = tid + 256 * i;
            int r = f >> 5, c4 = f & 31;
            ((float4*)Ws)[f] = *(const float4*)&W[(size_t)(kb + r) * ncols + c0 + c4 * 4];
        }
#pragma unroll
        for (int i = 0; i < 8; i++) {
            int f = tid + 256 * i;
            int m = f >> 5, k4 = f & 31;
            int row = r0 + m;
            float4 v = make_float4(0.f, 0.f, 0.f, 0.f);
            if (row < nrows) {
                v = *(const float4*)&X[(size_t)row * K + kb + k4 * 4];
                if (rowscale) {
                    float s = rowscale[row];
                    v.x *= s; v.y *= s; v.z *= s; v.w *= s;
                }
            }
            ((float4*)Xs)[f] = v;
        }
        __syncthreads();

#pragma unroll 2
        for (int k = 0; k < 128; k += 4) {
            float4 xv[8];
#pragma unroll
            for (int m = 0; m < 8; m++)
                xv[m] = *(const float4*)&Xs[(ty * 8 + m) * 128 + k];
#pragma unroll
            for (int kk = 0; kk < 4; kk++) {
                float4 w = *(const float4*)&Ws[(k + kk) * 128 + tx * 4];
#pragma unroll
                for (int m = 0; m < 8; m++) {
                    float xvv = (kk == 0) ? xv[m].x : (kk == 1) ? xv[m].y
                              : (kk == 2) ? xv[m].z : xv[m].w;
                    acc[m].x = fmaf(xvv, w.x, acc[m].x);
                    acc[m].y = fmaf(xvv, w.y, acc[m].y);
                    acc[m].z = fmaf(xvv, w.z, acc[m].z);
                    acc[m].w = fmaf(xvv, w.w, acc[m].w);
                }
            }
        }
        __syncthreads();
    }

    float4 b4 = make_float4(0.f, 0.f, 0.f, 0.f);
    if (bias) b4 = *(const float4*)&bias[c0 + tx * 4];
#pragma unroll
    for (int m = 0; m < 8; m++) {
        int row = r0 + ty * 8 + m;
        if (row < nrows) {
            float4 o;
            o.x = acc[m].x + b4.x; o.y = acc[m].y + b4.y;
            o.z = acc[m].z + b4.z; o.w = acc[m].w + b4.w;
            if (do_relu) {
                o.x = fmaxf(o.x, 0.f); o.y = fmaxf(o.y, 0.f);
                o.z = fmaxf(o.z, 0.f); o.w = fmaxf(o.w, 0.f);
            }
            *(float4*)&Y[(size_t)row * ncols + c0 + tx * 4] = o;
        }
    }
}

// ---------------- edge scatter: C[dst] += B[src]  (warp per edge, float4 red) ----------------
__global__ void k_scatter(const int* __restrict__ src, const int* __restrict__ dst) {
    int g = blockIdx.x * blockDim.x + threadIdx.x;
    int e = g >> 5;
    int lane = threadIdx.x & 31;
    if (e >= EE) return;
    int s = src[e], d = dst[e];
    float4 v = ((const float4*)(g_bufB + (size_t)s * DD))[lane];
    atomicAdd(((float4*)(g_bufC + (size_t)d * DD)) + lane, v);
}

// ---------------- y = relu(C*norm_dst + bg) + R  -> A ----------------
__global__ void k_combine(const float* __restrict__ bg) {
    int idx = blockIdx.x * blockDim.x + threadIdx.x;  // N*32 float4s
    if (idx >= NN * 32) return;
    int row = idx >> 5, j4 = idx & 31;
    float nd = g_norm_dst[row];
    float4 c = ((const float4*)g_bufC)[idx];
    float4 b4 = ((const float4*)bg)[j4];
    float4 r = ((const float4*)g_bufR)[idx];
    float4 o;
    o.x = fmaxf(fmaf(c.x, nd, b4.x), 0.f) + r.x;
    o.y = fmaxf(fmaf(c.y, nd, b4.y), 0.f) + r.y;
    o.z = fmaxf(fmaf(c.z, nd, b4.z), 0.f) + r.z;
    o.w = fmaxf(fmaf(c.w, nd, b4.w), 0.f) + r.w;
    ((float4*)g_bufA)[idx] = o;
}

// ---------------- BatchNorm ----------------
__global__ void k_bn_stats() {
    int j = threadIdx.x;  // 128 threads, one column each
    float s = 0.f, sq = 0.f;
    for (int r = blockIdx.x; r < NN; r += gridDim.x) {
        float v = g_bufA[(size_t)r * DD + j];
        s += v; sq += v * v;
    }
    atomicAdd(&g_stats[j], s);
    atomicAdd(&g_stats[DD + j], sq);
}

__global__ void k_bn_norm(const float* __restrict__ gamma, const float* __restrict__ beta) {
    int idx = blockIdx.x * blockDim.x + threadIdx.x;  // N*32 float4s
    if (idx >= NN * 32) return;
    int j4 = idx & 31;
    float4 sum = ((const float4*)g_stats)[j4];
    float4 sq  = ((const float4*)g_stats)[32 + j4];
    float4 ga  = ((const float4*)gamma)[j4];
    float4 be  = ((const float4*)beta)[j4];
    const float invN = 1.0f / (float)NN;
    float4 mu, iv;
    mu.x = sum.x * invN; mu.y = sum.y * invN; mu.z = sum.z * invN; mu.w = sum.w * invN;
    iv.x = rsqrtf(fmaxf(sq.x * invN - mu.x * mu.x, 0.f) + BN_EPS);
    iv.y = rsqrtf(fmaxf(sq.y * invN - mu.y * mu.y, 0.f) + BN_EPS);
    iv.z = rsqrtf(fmaxf(sq.z * invN - mu.z * mu.z, 0.f) + BN_EPS);
    iv.w = rsqrtf(fmaxf(sq.w * invN - mu.w * mu.w, 0.f) + BN_EPS);
    float4 v = ((const float4*)g_bufA)[idx];
    float4 o;
    o.x = (v.x - mu.x) * iv.x * ga.x + be.x;
    o.y = (v.y - mu.y) * iv.y * ga.y + be.y;
    o.z = (v.z - mu.z) * iv.z * ga.z + be.z;
    o.w = (v.w - mu.w) * iv.w * ga.w + be.w;
    ((float4*)g_bufA)[idx] = o;
}

// ---------------- pooling ----------------
__global__ void k_pool(const int* __restrict__ gid, const int* __restrict__ mid) {
    int g = blockIdx.x * blockDim.x + threadIdx.x;
    int node = g >> 5;
    int lane = threadIdx.x & 31;
    if (node >= NN) return;
    float4 v = ((const float4*)(g_bufA + (size_t)node * DD))[lane];
    atomicAdd(((float4*)(g_gsum + (size_t)gid[node] * DD)) + lane, v);
    atomicAdd(((float4*)(g_msum + (size_t)mid[node] * DD)) + lane, v);
}

__global__ void k_counts(const int* __restrict__ gid, const int* __restrict__ mid) {
    int i = blockIdx.x * blockDim.x + threadIdx.x;
    if (i < NN) {
        atomicAdd(&g_gcnt[gid[i]], 1.0f);
        atomicAdd(&g_mcnt[mid[i]], 1.0f);
    }
}

__global__ void k_finalize(float* __restrict__ out_gf) {
    int idx = blockIdx.x * blockDim.x + threadIdx.x;  // (G+M)*D
    if (idx >= (GG + MM) * DD) return;
    int row = idx / DD, j = idx % DD;
    float v;
    if (row < GG) {
        v = g_gsum[row * DD + j] / fmaxf(g_gcnt[row], 1.0f);
        out_gf[row * DD + j] = v;
    } else {
        int mrow = row - GG + 1;  // drop motif segment 0
        v = g_msum[mrow * DD + j] / fmaxf(g_mcnt[mrow], 1.0f);
    }
    g_headin[idx] = v;
}

// ---------------- launch ----------------
extern "C" void kernel_launch(void* const* d_in, const int* in_sizes, int n_in,
                              void* d_out, int out_size) {
    const float* node_feats = (const float*)d_in[0];
    const int*   src        = (const int*)d_in[1];
    const int*   dst        = (const int*)d_in[2];
    const int*   gid        = (const int*)d_in[3];
    const int*   mid        = (const int*)d_in[4];
    const float* Wg         = (const float*)d_in[5];
    const float* bg         = (const float*)d_in[6];
    const float* Wr         = (const float*)d_in[7];
    const float* br         = (const float*)d_in[8];
    const float* gamma      = (const float*)d_in[9];
    const float* beta       = (const float*)d_in[10];
    const float* W_feat     = (const float*)d_in[11];
    const float* b_feat     = (const float*)d_in[12];
    const float* W1         = (const float*)d_in[13];
    const float* b1         = (const float*)d_in[14];
    const float* W2         = (const float*)d_in[15];
    const float* b2         = (const float*)d_in[16];
    float* out = (float*)d_out;

    void *pA, *pB, *pC, *pR, *pns, *pnd, *pstats, *pgsum, *pgcnt, *pmsum, *pmcnt, *phin, *ph1, *ph2;
    cudaGetSymbolAddress(&pA, g_bufA);
    cudaGetSymbolAddress(&pB, g_bufB);
    cudaGetSymbolAddress(&pC, g_bufC);
    cudaGetSymbolAddress(&pR, g_bufR);
    cudaGetSymbolAddress(&pns, g_norm_src);
    cudaGetSymbolAddress(&pnd, g_norm_dst);
    cudaGetSymbolAddress(&pstats, g_stats);
    cudaGetSymbolAddress(&pgsum, g_gsum);
    cudaGetSymbolAddress(&pgcnt, g_gcnt);
    cudaGetSymbolAddress(&pmsum, g_msum);
    cudaGetSymbolAddress(&pmcnt, g_mcnt);
    cudaGetSymbolAddress(&phin, g_headin);
    cudaGetSymbolAddress(&ph1, g_head1);
    cudaGetSymbolAddress(&ph2, g_head2);

    const int SMEM_G = (128 * 128 + 64 * 128) * 4;                  // 96 KB (fp32 gemm)
    const int SMEM_D = (64 * 128 + 128 * 128 + 128 * 128) * 4;      // 160 KB (dual tf32)
    cudaFuncSetAttribute(k_gemm, cudaFuncAttributeMaxDynamicSharedMemorySize, SMEM_G);
    cudaFuncSetAttribute(k_dualgemm, cudaFuncAttributeMaxDynamicSharedMemorySize, SMEM_D);

    // degrees -> norms
    cudaMemsetAsync(pns, 0, NN * sizeof(float));
    cudaMemsetAsync(pnd, 0, NN * sizeof(float));
    k_degrees<<<(EE + 255) / 256, 256>>>(src, dst);
    k_norms<<<(NN + 255) / 256, 256>>>();

    const int gemm_blocks = (NN + 63) / 64;           // 782
    const int elw_blocks = (NN * 32 + 255) / 256;     // 6250
    const int scat_blocks = (EE * 32 + 255) / 256;    // 75000

    for (int l = 0; l < LL; l++) {
        const float* hin = (l == 0) ? node_feats : (const float*)pA;

        // B = rowscale .* (h @ Wg[l]);  R = relu(h @ Wr[l] + br[l])  (one fused tf32 kernel)
        k_dualgemm<<<gemm_blocks, 256, SMEM_D>>>(
            hin, Wg + (size_t)l * DD * DD, Wr + (size_t)l * DD * DD,
            br + (size_t)l * DD, (const float*)pns,
            (float*)pB, (float*)pR, NN);

        // agg: C = 0; C[dst] += B[src]
        cudaMemsetAsync(pC, 0, (size_t)NN * DD * sizeof(float));
        k_scatter<<<scat_blocks, 256>>>(src, dst);

        // y = relu(C*norm_dst + bg) + R -> A
        k_combine<<<elw_blocks, 256>>>(bg + (size_t)l * DD);

        // BatchNorm (training stats, biased var)
        cudaMemsetAsync(pstats, 0, 2 * DD * sizeof(float));
        k_bn_stats<<<512, 128>>>();
        k_bn_norm<<<elw_blocks, 256>>>(gamma + (size_t)l * DD, beta + (size_t)l * DD);
    }

    // pooling
    cudaMemsetAsync(pgsum, 0, (size_t)GG * DD * sizeof(float));
    cudaMemsetAsync(pgcnt, 0, GG * sizeof(float));
    cudaMemsetAsync(pmsum, 0, (size_t)(MM + 1) * DD * sizeof(float));
    cudaMemsetAsync(pmcnt, 0, (MM + 1) * sizeof(float));
    k_pool<<<(NN * 32 + 255) / 256, 256>>>(gid, mid);
    k_counts<<<(NN + 255) / 256, 256>>>(gid, mid);
    k_finalize<<<((GG + MM) * DD + 255) / 256, 256>>>(out);

    // head MLP on combined [graph_feats ; h_sub] = 2560 rows,
    // final GEMM writes out_global||out_sub contiguously into d_out.
    const int HR = GG + MM;              // 2560
    const int hblocks = (HR + 63) / 64;  // 40
    k_gemm<<<dim3(hblocks, FFN / 128), 256, SMEM_G>>>(
        (const float*)phin, W_feat, b_feat, nullptr, (float*)ph1, HR, DD, FFN, 0);
    k_gemm<<<dim3(hblocks, FFN / 128), 256, SMEM_G>>>(
        (const float*)ph1, W1, b1, nullptr, (float*)ph2, HR, FFN, FFN, 1);
    k_gemm<<<dim3(hblocks, 1), 256, SMEM_G>>>(
        (const float*)ph2, W2, b2, nullptr, out + (size_t)GG * DD, HR, FFN, DD, 0);
}

// round 3
// speedup vs baseline: 1.1296x; 1.1296x over previous
#include <cuda_runtime.h>
#include <cuda_bf16.h>
#include <cstddef>

#define NN 50000
#define EE 600000
#define GG 512
#define MM 2048
#define DD 128
#define FFN 256
#define LL 3
#define BN_EPS 1e-5f

// ---------------- scratch (device globals) ----------------
__device__ float g_bufA[NN * DD];   // layer output h
__device__ float g_bufB[NN * DD];   // hw branch
__device__ float g_bufR[NN * DD];   // residual branch
__device__ int   g_degin[NN];
__device__ int   g_degout[NN];
__device__ int   g_cursor[NN];
__device__ int   g_rowstart[NN + 1];
__device__ int   g_csr_src[EE];
__device__ float g_norm_src[NN];
__device__ float g_norm_dst[NN];
__device__ float g_stats[2 * DD];
__device__ float g_cs[DD];
__device__ float g_cb[DD];
__device__ float g_gsum[GG * DD];
__device__ float g_gcnt[GG];
__device__ float g_msum[(MM + 1) * DD];
__device__ float g_mcnt[MM + 1];
__device__ float g_headin[(GG + MM) * DD];
__device__ float g_head1[(GG + MM) * FFN];
__device__ float g_head2[(GG + MM) * FFN];

// ---------------- CSR build ----------------
__global__ void k_hist(const int* __restrict__ src, const int* __restrict__ dst) {
    int e = blockIdx.x * blockDim.x + threadIdx.x;
    if (e < EE) {
        atomicAdd(&g_degout[src[e]], 1);
        atomicAdd(&g_degin[dst[e]], 1);
    }
}

__global__ void k_norms() {
    int i = blockIdx.x * blockDim.x + threadIdx.x;
    if (i < NN) {
        g_norm_src[i] = rsqrtf(fmaxf((float)g_degout[i], 1.0f));
        g_norm_dst[i] = rsqrtf(fmaxf((float)g_degin[i], 1.0f));
    }
}

// single-block exclusive scan of g_degin -> g_rowstart
__global__ void k_scan() {
    const int T = 1024;
    __shared__ int buf[T];
    int tid = threadIdx.x;
    const int chunk = (NN + T - 1) / T;  // 49
    int base = tid * chunk;
    int s = 0;
    for (int i = 0; i < chunk; i++) {
        int idx = base + i;
        if (idx < NN) s += g_degin[idx];
    }
    buf[tid] = s;
    __syncthreads();
    // inclusive Hillis-Steele
    for (int off = 1; off < T; off <<= 1) {
        int t = (tid >= off) ? buf[tid - off] : 0;
        __syncthreads();
        buf[tid] += t;
        __syncthreads();
    }
    int running = buf[tid] - s;  // exclusive prefix of this chunk
    for (int i = 0; i < chunk; i++) {
        int idx = base + i;
        if (idx < NN) {
            g_rowstart[idx] = running;
            running += g_degin[idx];
        }
    }
    if (tid == 0) g_rowstart[NN] = EE;
}

__global__ void k_place(const int* __restrict__ src, const int* __restrict__ dst) {
    int e = blockIdx.x * blockDim.x + threadIdx.x;
    if (e < EE) {
        int d = dst[e];
        int slot = atomicAdd(&g_cursor[d], 1);
        g_csr_src[g_rowstart[d] + slot] = src[e];
    }
}

// ---------------- fused dual GEMM (fp32), BN affine folded into X load ----------------
// Y1 = rs .* (Xn @ W1)          Xn = X*cs + cb (per-column; identity if cs==nullptr)
// Y2 = relu(Xn @ W2 + b2)
__global__ void k_dualgemm(const float* __restrict__ X,
                           const float* __restrict__ W1,
                           const float* __restrict__ W2,
                           const float* __restrict__ b2,
                           const float* __restrict__ rs,
                           const float* __restrict__ cs,
                           const float* __restrict__ cb,
                           float* __restrict__ Y1, float* __restrict__ Y2,
                           int nrows) {
    extern __shared__ float sm[];
    float* Xs  = sm;               // 64*128
    float* W1s = sm + 64 * 128;    // 128*128
    float* W2s = W1s + 128 * 128;  // 128*128
    const int tid = threadIdx.x;
    const int tx = tid & 31;
    const int ty = tid >> 5;
    const int r0 = blockIdx.x * 64;

#pragma unroll
    for (int i = 0; i < 16; i++) {
        int f = tid + 256 * i;     // 4096 float4 each
        ((float4*)W1s)[f] = ((const float4*)W1)[f];
        ((float4*)W2s)[f] = ((const float4*)W2)[f];
    }
#pragma unroll
    for (int i = 0; i < 8; i++) {
        int f = tid + 256 * i;     // 2048 float4
        int row = r0 + (f >> 5);
        int j4 = f & 31;
        float4 v = make_float4(0.f, 0.f, 0.f, 0.f);
        if (row < nrows) {
            v = ((const float4*)(X + (size_t)row * DD))[j4];
            if (cs) {
                float4 s4 = ((const float4*)cs)[j4];
                float4 h4 = ((const float4*)cb)[j4];
                v.x = fmaf(v.x, s4.x, h4.x);
                v.y = fmaf(v.y, s4.y, h4.y);
                v.z = fmaf(v.z, s4.z, h4.z);
                v.w = fmaf(v.w, s4.w, h4.w);
            }
        }
        ((float4*)Xs)[f] = v;
    }
    __syncthreads();

    float4 acc1[8], acc2[8];
#pragma unroll
    for (int m = 0; m < 8; m++) {
        acc1[m] = make_float4(0.f, 0.f, 0.f, 0.f);
        acc2[m] = make_float4(0.f, 0.f, 0.f, 0.f);
    }

#pragma unroll 2
    for (int k = 0; k < 128; k += 4) {
        float4 xv[8];
#pragma unroll
        for (int m = 0; m < 8; m++)
            xv[m] = *(const float4*)&Xs[(ty * 8 + m) * 128 + k];
#pragma unroll
        for (int kk = 0; kk < 4; kk++) {
            float4 w1 = *(const float4*)&W1s[(k + kk) * 128 + tx * 4];
            float4 w2 = *(const float4*)&W2s[(k + kk) * 128 + tx * 4];
#pragma unroll
            for (int m = 0; m < 8; m++) {
                float xvv = (kk == 0) ? xv[m].x : (kk == 1) ? xv[m].y
                          : (kk == 2) ? xv[m].z : xv[m].w;
                acc1[m].x = fmaf(xvv, w1.x, acc1[m].x);
                acc1[m].y = fmaf(xvv, w1.y, acc1[m].y);
                acc1[m].z = fmaf(xvv, w1.z, acc1[m].z);
                acc1[m].w = fmaf(xvv, w1.w, acc1[m].w);
                acc2[m].x = fmaf(xvv, w2.x, acc2[m].x);
                acc2[m].y = fmaf(xvv, w2.y, acc2[m].y);
                acc2[m].z = fmaf(xvv, w2.z, acc2[m].z);
                acc2[m].w = fmaf(xvv, w2.w, acc2[m].w);
            }
        }
    }

    float4 b4 = ((const float4*)b2)[tx];
#pragma unroll
    for (int m = 0; m < 8; m++) {
        int row = r0 + ty * 8 + m;
        if (row < nrows) {
            float s = rs[row];
            float4 o1;
            o1.x = acc1[m].x * s; o1.y = acc1[m].y * s;
            o1.z = acc1[m].z * s; o1.w = acc1[m].w * s;
            ((float4*)(Y1 + (size_t)row * DD))[tx] = o1;
            float4 o2;
            o2.x = fmaxf(acc2[m].x + b4.x, 0.f);
            o2.y = fmaxf(acc2[m].y + b4.y, 0.f);
            o2.z = fmaxf(acc2[m].z + b4.z, 0.f);
            o2.w = fmaxf(acc2[m].w + b4.w, 0.f);
            ((float4*)(Y2 + (size_t)row * DD))[tx] = o2;
        }
    }
}

// ---------------- CSR aggregation + combine + BN stats (fused) ----------------
// A[n] = relu( (sum_{e in in(n)} B[src_e]) * norm_dst[n] + bg ) + R[n]
// plus blockwise column sums / sumsq accumulated into g_stats.
__global__ void k_agg(const float* __restrict__ bg) {
    __shared__ float ssum[DD];
    __shared__ float ssq[DD];
    int tid = threadIdx.x;
    if (tid < DD) { ssum[tid] = 0.f; ssq[tid] = 0.f; }
    __syncthreads();

    int node = blockIdx.x * 8 + (tid >> 5);
    int lane = tid & 31;
    if (node < NN) {
        int e0 = g_rowstart[node], e1 = g_rowstart[node + 1];
        float4 acc = make_float4(0.f, 0.f, 0.f, 0.f);
        float4 acc2 = make_float4(0.f, 0.f, 0.f, 0.f);
        int e = e0;
        for (; e + 2 <= e1; e += 2) {
            int s0 = g_csr_src[e];
            int s1 = g_csr_src[e + 1];
            float4 v0 = ((const float4*)(g_bufB + (size_t)s0 * DD))[lane];
            float4 v1 = ((const float4*)(g_bufB + (size_t)s1 * DD))[lane];
            acc.x += v0.x; acc.y += v0.y; acc.z += v0.z; acc.w += v0.w;
            acc2.x += v1.x; acc2.y += v1.y; acc2.z += v1.z; acc2.w += v1.w;
        }
        if (e < e1) {
            int s0 = g_csr_src[e];
            float4 v0 = ((const float4*)(g_bufB + (size_t)s0 * DD))[lane];
            acc.x += v0.x; acc.y += v0.y; acc.z += v0.z; acc.w += v0.w;
        }
        acc.x += acc2.x; acc.y += acc2.y; acc.z += acc2.z; acc.w += acc2.w;

        float nd = g_norm_dst[node];
        float4 b4 = ((const float4*)bg)[lane];
        float4 r = ((const float4*)(g_bufR + (size_t)node * DD))[lane];
        float4 y;
        y.x = fmaxf(fmaf(acc.x, nd, b4.x), 0.f) + r.x;
        y.y = fmaxf(fmaf(acc.y, nd, b4.y), 0.f) + r.y;
        y.z = fmaxf(fmaf(acc.z, nd, b4.z), 0.f) + r.z;
        y.w = fmaxf(fmaf(acc.w, nd, b4.w), 0.f) + r.w;
        ((float4*)(g_bufA + (size_t)node * DD))[lane] = y;

        atomicAdd(&ssum[lane * 4 + 0], y.x);
        atomicAdd(&ssum[lane * 4 + 1], y.y);
        atomicAdd(&ssum[lane * 4 + 2], y.z);
        atomicAdd(&ssum[lane * 4 + 3], y.w);
        atomicAdd(&ssq[lane * 4 + 0], y.x * y.x);
        atomicAdd(&ssq[lane * 4 + 1], y.y * y.y);
        atomicAdd(&ssq[lane * 4 + 2], y.z * y.z);
        atomicAdd(&ssq[lane * 4 + 3], y.w * y.w);
    }
    __syncthreads();
    if (tid < DD) {
        atomicAdd(&g_stats[tid], ssum[tid]);
        atomicAdd(&g_stats[DD + tid], ssq[tid]);
    }
}

// ---------------- BN prep: cs = gamma*iv, cb = beta - mu*cs ----------------
__global__ void k_bnprep(const float* __restrict__ gamma, const float* __restrict__ beta) {
    int j = threadIdx.x;
    float invN = 1.0f / (float)NN;
    float mu = g_stats[j] * invN;
    float var = fmaxf(g_stats[DD + j] * invN - mu * mu, 0.f);
    float s = gamma[j] * rsqrtf(var + BN_EPS);
    g_cs[j] = s;
    g_cb[j] = beta[j] - mu * s;
}

// ---------------- pooling (BN affine applied here) + counts ----------------
__global__ void k_pool(const int* __restrict__ gid, const int* __restrict__ mid) {
    int g = blockIdx.x * blockDim.x + threadIdx.x;
    int node = g >> 5;
    int lane = threadIdx.x & 31;
    if (node >= NN) return;
    float4 v = ((const float4*)(g_bufA + (size_t)node * DD))[lane];
    float4 s4 = ((const float4*)g_cs)[lane];
    float4 h4 = ((const float4*)g_cb)[lane];
    v.x = fmaf(v.x, s4.x, h4.x);
    v.y = fmaf(v.y, s4.y, h4.y);
    v.z = fmaf(v.z, s4.z, h4.z);
    v.w = fmaf(v.w, s4.w, h4.w);
    int gi = gid[node], mi = mid[node];
    atomicAdd(((float4*)(g_gsum + (size_t)gi * DD)) + lane, v);
    atomicAdd(((float4*)(g_msum + (size_t)mi * DD)) + lane, v);
    if (lane == 0) {
        atomicAdd(&g_gcnt[gi], 1.0f);
        atomicAdd(&g_mcnt[mi], 1.0f);
    }
}

__global__ void k_finalize(float* __restrict__ out_gf) {
    int idx = blockIdx.x * blockDim.x + threadIdx.x;  // (G+M)*D
    if (idx >= (GG + MM) * DD) return;
    int row = idx / DD, j = idx % DD;
    float v;
    if (row < GG) {
        v = g_gsum[row * DD + j] / fmaxf(g_gcnt[row], 1.0f);
        out_gf[row * DD + j] = v;
    } else {
        int mrow = row - GG + 1;  // drop motif segment 0
        v = g_msum[mrow * DD + j] / fmaxf(g_mcnt[mrow], 1.0f);
    }
    g_headin[idx] = v;
}

// ---------------- fp32 tiled GEMM (head MLP) ----------------
__global__ void k_gemm(const float* __restrict__ X, const float* __restrict__ W,
                       const float* __restrict__ bias,
                       float* __restrict__ Y, int nrows, int K, int ncols, int do_relu) {
    extern __shared__ float sm[];
    float* Ws = sm;               // 128*128
    float* Xs = sm + 128 * 128;   // 64*128
    const int tid = threadIdx.x;
    const int tx = tid & 31;
    const int ty = tid >> 5;
    const int r0 = blockIdx.x * 64;
    const int c0 = blockIdx.y * 128;

    float4 acc[8];
#pragma unroll
    for (int m = 0; m < 8; m++) acc[m] = make_float4(0.f, 0.f, 0.f, 0.f);

    for (int kb = 0; kb < K; kb += 128) {
#pragma unroll
        for (int i = 0; i < 16; i++) {
            int f = tid + 256 * i;
            int r = f >> 5, c4 = f & 31;
            ((float4*)Ws)[f] = *(const float4*)&W[(size_t)(kb + r) * ncols + c0 + c4 * 4];
        }
#pragma unroll
        for (int i = 0; i < 8; i++) {
            int f = tid + 256 * i;
            int m = f >> 5, k4 = f & 31;
            int row = r0 + m;
            float4 v = make_float4(0.f, 0.f, 0.f, 0.f);
            if (row < nrows) v = *(const float4*)&X[(size_t)row * K + kb + k4 * 4];
            ((float4*)Xs)[f] = v;
        }
        __syncthreads();

#pragma unroll 2
        for (int k = 0; k < 128; k += 4) {
            float4 xv[8];
#pragma unroll
            for (int m = 0; m < 8; m++)
                xv[m] = *(const float4*)&Xs[(ty * 8 + m) * 128 + k];
#pragma unroll
            for (int kk = 0; kk < 4; kk++) {
                float4 w = *(const float4*)&Ws[(k + kk) * 128 + tx * 4];
#pragma unroll
                for (int m = 0; m < 8; m++) {
                    float xvv = (kk == 0) ? xv[m].x : (kk == 1) ? xv[m].y
                              : (kk == 2) ? xv[m].z : xv[m].w;
                    acc[m].x = fmaf(xvv, w.x, acc[m].x);
                    acc[m].y = fmaf(xvv, w.y, acc[m].y);
                    acc[m].z = fmaf(xvv, w.z, acc[m].z);
                    acc[m].w = fmaf(xvv, w.w, acc[m].w);
                }
            }
        }
        __syncthreads();
    }

    float4 b4 = make_float4(0.f, 0.f, 0.f, 0.f);
    if (bias) b4 = *(const float4*)&bias[c0 + tx * 4];
#pragma unroll
    for (int m = 0; m < 8; m++) {
        int row = r0 + ty * 8 + m;
        if (row < nrows) {
            float4 o;
            o.x = acc[m].x + b4.x; o.y = acc[m].y + b4.y;
            o.z = acc[m].z + b4.z; o.w = acc[m].w + b4.w;
            if (do_relu) {
                o.x = fmaxf(o.x, 0.f); o.y = fmaxf(o.y, 0.f);
                o.z = fmaxf(o.z, 0.f); o.w = fmaxf(o.w, 0.f);
            }
            *(float4*)&Y[(size_t)row * ncols + c0 + tx * 4] = o;
        }
    }
}

// ---------------- launch ----------------
extern "C" void kernel_launch(void* const* d_in, const int* in_sizes, int n_in,
                              void* d_out, int out_size) {
    const float* node_feats = (const float*)d_in[0];
    const int*   src        = (const int*)d_in[1];
    const int*   dst        = (const int*)d_in[2];
    const int*   gid        = (const int*)d_in[3];
    const int*   mid        = (const int*)d_in[4];
    const float* Wg         = (const float*)d_in[5];
    const float* bg         = (const float*)d_in[6];
    const float* Wr         = (const float*)d_in[7];
    const float* br         = (const float*)d_in[8];
    const float* gamma      = (const float*)d_in[9];
    const float* beta       = (const float*)d_in[10];
    const float* W_feat     = (const float*)d_in[11];
    const float* b_feat     = (const float*)d_in[12];
    const float* W1         = (const float*)d_in[13];
    const float* b1         = (const float*)d_in[14];
    const float* W2         = (const float*)d_in[15];
    const float* b2         = (const float*)d_in[16];
    float* out = (float*)d_out;

    void *pA, *pB, *pR, *pdi, *pdo, *pcur, *pns, *pstats,
         *pgsum, *pgcnt, *pmsum, *pmcnt, *phin, *ph1, *ph2;
    cudaGetSymbolAddress(&pA, g_bufA);
    cudaGetSymbolAddress(&pB, g_bufB);
    cudaGetSymbolAddress(&pR, g_bufR);
    cudaGetSymbolAddress(&pdi, g_degin);
    cudaGetSymbolAddress(&pdo, g_degout);
    cudaGetSymbolAddress(&pcur, g_cursor);
    cudaGetSymbolAddress(&pns, g_norm_src);
    cudaGetSymbolAddress(&pstats, g_stats);
    cudaGetSymbolAddress(&pgsum, g_gsum);
    cudaGetSymbolAddress(&pgcnt, g_gcnt);
    cudaGetSymbolAddress(&pmsum, g_msum);
    cudaGetSymbolAddress(&pmcnt, g_mcnt);
    cudaGetSymbolAddress(&phin, g_headin);
    cudaGetSymbolAddress(&ph1, g_head1);
    cudaGetSymbolAddress(&ph2, g_head2);

    const int SMEM_G = (128 * 128 + 64 * 128) * 4;               // 96 KB
    const int SMEM_D = (64 * 128 + 2 * 128 * 128) * 4;           // 160 KB
    cudaFuncSetAttribute(k_gemm, cudaFuncAttributeMaxDynamicSharedMemorySize, SMEM_G);
    cudaFuncSetAttribute(k_dualgemm, cudaFuncAttributeMaxDynamicSharedMemorySize, SMEM_D);

    // ---- CSR build + norms ----
    cudaMemsetAsync(pdi, 0, NN * sizeof(int));
    cudaMemsetAsync(pdo, 0, NN * sizeof(int));
    cudaMemsetAsync(pcur, 0, NN * sizeof(int));
    k_hist<<<(EE + 255) / 256, 256>>>(src, dst);
    k_norms<<<(NN + 255) / 256, 256>>>();
    k_scan<<<1, 1024>>>();
    k_place<<<(EE + 255) / 256, 256>>>(src, dst);

    const int gemm_blocks = (NN + 63) / 64;   // 782
    const int agg_blocks = (NN + 7) / 8;      // 6250

    for (int l = 0; l < LL; l++) {
        const float* hin = (l == 0) ? node_feats : (const float*)pA;
        const float* cs = (l == 0) ? nullptr : g_cs;  // device symbol addr via kernel arg
        // NOTE: g_cs/g_cb referenced inside kernels via symbols when null passed;
        // here we pass explicit pointers:
        void *pcs, *pcb;
        cudaGetSymbolAddress(&pcs, g_cs);
        cudaGetSymbolAddress(&pcb, g_cb);

        // B = norm_src .* (Xn @ Wg[l]);  R = relu(Xn @ Wr[l] + br[l])
        k_dualgemm<<<gemm_blocks, 256, SMEM_D>>>(
            hin, Wg + (size_t)l * DD * DD, Wr + (size_t)l * DD * DD,
            br + (size_t)l * DD, (const float*)pns,
            (l == 0) ? nullptr : (const float*)pcs,
            (l == 0) ? nullptr : (const float*)pcb,
            (float*)pB, (float*)pR, NN);

        // stats <- 0; A = relu(agg*nd + bg) + R; stats accumulated
        cudaMemsetAsync(pstats, 0, 2 * DD * sizeof(float));
        k_agg<<<agg_blocks, 256>>>(bg + (size_t)l * DD);

        // fold BN into affine cs/cb for next consumer
        k_bnprep<<<1, DD>>>(gamma + (size_t)l * DD, beta + (size_t)l * DD);
    }

    // ---- pooling (applies layer-2 BN affine) ----
    cudaMemsetAsync(pgsum, 0, (size_t)GG * DD * sizeof(float));
    cudaMemsetAsync(pgcnt, 0, GG * sizeof(float));
    cudaMemsetAsync(pmsum, 0, (size_t)(MM + 1) * DD * sizeof(float));
    cudaMemsetAsync(pmcnt, 0, (MM + 1) * sizeof(float));
    k_pool<<<(NN * 32 + 255) / 256, 256>>>(gid, mid);
    k_finalize<<<((GG + MM) * DD + 255) / 256, 256>>>(out);

    // ---- head MLP on [graph_feats ; h_sub] = 2560 rows ----
    const int HR = GG + MM;
    const int hblocks = (HR + 63) / 64;  // 40
    k_gemm<<<dim3(hblocks, FFN / 128), 256, SMEM_G>>>(
        (const float*)phin, W_feat, b_feat, (float*)ph1, HR, DD, FFN, 0);
    k_gemm<<<dim3(hblocks, FFN / 128), 256, SMEM_G>>>(
        (const float*)ph1, W1, b1, (float*)ph2, HR, FFN, FFN, 1);
    k_gemm<<<dim3(hblocks, 1), 256, SMEM_G>>>(
        (const float*)ph2, W2, b2, out + (size_t)GG * DD, HR, FFN, DD, 0);
}

// round 4
// speedup vs baseline: 1.1675x; 1.0336x over previous
#include <cuda_runtime.h>
#include <cuda_bf16.h>
#include <cstddef>

#define NN 50000
#define EE 600000
#define GG 512
#define MM 2048
#define DD 128
#define FFN 256
#define LL 3
#define BN_EPS 1e-5f

// ---------------- scratch (device globals) ----------------
__device__ float g_bufA[NN * DD];   // layer output h
__device__ float g_bufB[NN * DD];   // hw branch
__device__ float g_bufR[NN * DD];   // residual branch
__device__ int   g_degin[NN];
__device__ int   g_degout[NN];
__device__ int   g_cursor[NN];
__device__ int   g_rowstart[NN + 1];
__device__ int   g_csr_src[EE];
__device__ float g_norm_src[NN];
__device__ float g_norm_dst[NN];
__device__ float g_stats[2 * DD];
__device__ float g_cs[DD];
__device__ float g_cb[DD];
__device__ float g_gsum[GG * DD];
__device__ float g_gcnt[GG];
__device__ float g_msum[(MM + 1) * DD];
__device__ float g_mcnt[MM + 1];
__device__ float g_headin[(GG + MM) * DD];
__device__ float g_head1[(GG + MM) * FFN];
__device__ float g_head2[(GG + MM) * FFN];

// ---------------- f32x2 helpers ----------------
__device__ __forceinline__ unsigned long long pack_dup(float x) {
    unsigned long long p;
    unsigned int xb = __float_as_uint(x);
    asm("mov.b64 %0, {%1, %1};" : "=l"(p) : "r"(xb));
    return p;
}
__device__ __forceinline__ void ffma2(unsigned long long& acc, unsigned long long a,
                                      unsigned long long b) {
    asm("fma.rn.f32x2 %0, %1, %2, %0;" : "+l"(acc) : "l"(a), "l"(b));
}
__device__ __forceinline__ float2 unpack2(unsigned long long a) {
    float lo, hi;
    asm("mov.b64 {%0, %1}, %2;" : "=f"(lo), "=f"(hi) : "l"(a));
    return make_float2(lo, hi);
}

// ---------------- CSR build ----------------
__global__ void k_hist(const int* __restrict__ src, const int* __restrict__ dst) {
    int e = blockIdx.x * blockDim.x + threadIdx.x;
    if (e < EE) {
        atomicAdd(&g_degout[src[e]], 1);
        atomicAdd(&g_degin[dst[e]], 1);
    }
}

__global__ void k_norms() {
    int i = blockIdx.x * blockDim.x + threadIdx.x;
    if (i < NN) {
        g_norm_src[i] = rsqrtf(fmaxf((float)g_degout[i], 1.0f));
        g_norm_dst[i] = rsqrtf(fmaxf((float)g_degin[i], 1.0f));
    }
    if (i < 2 * DD) g_stats[i] = 0.f;   // zero BN stats for layer 0
}

// single-block exclusive scan of g_degin -> g_rowstart (also zeroes g_cursor)
__global__ void k_scan() {
    const int T = 1024;
    __shared__ int buf[T];
    int tid = threadIdx.x;
    const int chunk = (NN + T - 1) / T;
    int base = tid * chunk;
    int s = 0;
    for (int i = 0; i < chunk; i++) {
        int idx = base + i;
        if (idx < NN) { s += g_degin[idx]; g_cursor[idx] = 0; }
    }
    buf[tid] = s;
    __syncthreads();
    for (int off = 1; off < T; off <<= 1) {
        int t = (tid >= off) ? buf[tid - off] : 0;
        __syncthreads();
        buf[tid] += t;
        __syncthreads();
    }
    int running = buf[tid] - s;
    for (int i = 0; i < chunk; i++) {
        int idx = base + i;
        if (idx < NN) {
            g_rowstart[idx] = running;
            running += g_degin[idx];
        }
    }
    if (tid == 0) g_rowstart[NN] = EE;
}

__global__ void k_place(const int* __restrict__ src, const int* __restrict__ dst) {
    int e = blockIdx.x * blockDim.x + threadIdx.x;
    if (e < EE) {
        int d = dst[e];
        int slot = atomicAdd(&g_cursor[d], 1);
        g_csr_src[g_rowstart[d] + slot] = src[e];
    }
}

// ---------------- fused dual GEMM (fp32, f32x2 FFMA2), BN affine folded into X load ----------------
// Y1 = rs .* (Xn @ W1)      Xn = X*cs + cb (per-column; identity if cs==nullptr)
// Y2 = relu(Xn @ W2 + b2)
__global__ void k_dualgemm(const float* __restrict__ X,
                           const float* __restrict__ W1,
                           const float* __restrict__ W2,
                           const float* __restrict__ b2,
                           const float* __restrict__ rs,
                           const float* __restrict__ cs,
                           const float* __restrict__ cb,
                           float* __restrict__ Y1, float* __restrict__ Y2,
                           int nrows) {
    extern __shared__ float sm[];
    float* Xs  = sm;               // 64*128
    float* W1s = sm + 64 * 128;    // 128*128
    float* W2s = W1s + 128 * 128;  // 128*128
    const int tid = threadIdx.x;
    const int tx = tid & 31;
    const int ty = tid >> 5;
    const int r0 = blockIdx.x * 64;

#pragma unroll
    for (int i = 0; i < 16; i++) {
        int f = tid + 256 * i;
        ((float4*)W1s)[f] = ((const float4*)W1)[f];
        ((float4*)W2s)[f] = ((const float4*)W2)[f];
    }
#pragma unroll
    for (int i = 0; i < 8; i++) {
        int f = tid + 256 * i;
        int row = r0 + (f >> 5);
        int j4 = f & 31;
        float4 v = make_float4(0.f, 0.f, 0.f, 0.f);
        if (row < nrows) {
            v = ((const float4*)(X + (size_t)row * DD))[j4];
            if (cs) {
                float4 s4 = ((const float4*)cs)[j4];
                float4 h4 = ((const float4*)cb)[j4];
                v.x = fmaf(v.x, s4.x, h4.x);
                v.y = fmaf(v.y, s4.y, h4.y);
                v.z = fmaf(v.z, s4.z, h4.z);
                v.w = fmaf(v.w, s4.w, h4.w);
            }
        }
        ((float4*)Xs)[f] = v;
    }
    __syncthreads();

    unsigned long long a1[8][2], a2[8][2];
#pragma unroll
    for (int m = 0; m < 8; m++) {
        a1[m][0] = a1[m][1] = 0ull;
        a2[m][0] = a2[m][1] = 0ull;
    }

#pragma unroll 2
    for (int k = 0; k < 128; k += 4) {
        float4 xv[8];
#pragma unroll
        for (int m = 0; m < 8; m++)
            xv[m] = *(const float4*)&Xs[(ty * 8 + m) * 128 + k];
#pragma unroll
        for (int kk = 0; kk < 4; kk++) {
            ulonglong2 w1 = *(const ulonglong2*)&W1s[(k + kk) * 128 + tx * 4];
            ulonglong2 w2 = *(const ulonglong2*)&W2s[(k + kk) * 128 + tx * 4];
#pragma unroll
            for (int m = 0; m < 8; m++) {
                float x = (kk == 0) ? xv[m].x : (kk == 1) ? xv[m].y
                        : (kk == 2) ? xv[m].z : xv[m].w;
                unsigned long long xp = pack_dup(x);
                ffma2(a1[m][0], xp, w1.x);
                ffma2(a1[m][1], xp, w1.y);
                ffma2(a2[m][0], xp, w2.x);
                ffma2(a2[m][1], xp, w2.y);
            }
        }
    }

    float4 b4 = ((const float4*)b2)[tx];
#pragma unroll
    for (int m = 0; m < 8; m++) {
        int row = r0 + ty * 8 + m;
        if (row < nrows) {
            float s = rs[row];
            float2 p0 = unpack2(a1[m][0]);
            float2 p1 = unpack2(a1[m][1]);
            float4 o1 = make_float4(p0.x * s, p0.y * s, p1.x * s, p1.y * s);
            ((float4*)(Y1 + (size_t)row * DD))[tx] = o1;
            float2 q0 = unpack2(a2[m][0]);
            float2 q1 = unpack2(a2[m][1]);
            float4 o2;
            o2.x = fmaxf(q0.x + b4.x, 0.f);
            o2.y = fmaxf(q0.y + b4.y, 0.f);
            o2.z = fmaxf(q1.x + b4.z, 0.f);
            o2.w = fmaxf(q1.y + b4.w, 0.f);
            ((float4*)(Y2 + (size_t)row * DD))[tx] = o2;
        }
    }
}

// ---------------- CSR aggregation + combine + BN stats (fused) ----------------
// A[n] = relu( (sum_{e in in(n)} B[src_e]) * norm_dst[n] + bg ) + R[n]
// stats via per-warp smem partials + tree reduce (no smem atomics).
// zpool: additionally zero the pooling buffers (layer 2 only).
__global__ void k_agg(const float* __restrict__ bg, int zpool) {
    __shared__ float ssum[8][DD];
    __shared__ float ssq[8][DD];
    int tid = threadIdx.x;
    int w = tid >> 5;
    int lane = tid & 31;

    if (zpool) {
        int gstep = gridDim.x * blockDim.x;
        int gidx = blockIdx.x * blockDim.x + tid;
        for (int i = gidx; i < GG * DD; i += gstep) g_gsum[i] = 0.f;
        for (int i = gidx; i < (MM + 1) * DD; i += gstep) g_msum[i] = 0.f;
        for (int i = gidx; i < GG; i += gstep) g_gcnt[i] = 0.f;
        for (int i = gidx; i < MM + 1; i += gstep) g_mcnt[i] = 0.f;
    }

    int node = blockIdx.x * 8 + w;
    float4 y = make_float4(0.f, 0.f, 0.f, 0.f);
    if (node < NN) {
        int e0 = g_rowstart[node], e1 = g_rowstart[node + 1];
        float4 acc0 = make_float4(0.f, 0.f, 0.f, 0.f);
        float4 acc1 = make_float4(0.f, 0.f, 0.f, 0.f);
        float4 acc2 = make_float4(0.f, 0.f, 0.f, 0.f);
        float4 acc3 = make_float4(0.f, 0.f, 0.f, 0.f);
        int e = e0;
        for (; e + 4 <= e1; e += 4) {
            int s0 = g_csr_src[e], s1 = g_csr_src[e + 1];
            int s2 = g_csr_src[e + 2], s3 = g_csr_src[e + 3];
            float4 v0 = ((const float4*)(g_bufB + (size_t)s0 * DD))[lane];
            float4 v1 = ((const float4*)(g_bufB + (size_t)s1 * DD))[lane];
            float4 v2 = ((const float4*)(g_bufB + (size_t)s2 * DD))[lane];
            float4 v3 = ((const float4*)(g_bufB + (size_t)s3 * DD))[lane];
            acc0.x += v0.x; acc0.y += v0.y; acc0.z += v0.z; acc0.w += v0.w;
            acc1.x += v1.x; acc1.y += v1.y; acc1.z += v1.z; acc1.w += v1.w;
            acc2.x += v2.x; acc2.y += v2.y; acc2.z += v2.z; acc2.w += v2.w;
            acc3.x += v3.x; acc3.y += v3.y; acc3.z += v3.z; acc3.w += v3.w;
        }
        for (; e < e1; e++) {
            int s0 = g_csr_src[e];
            float4 v0 = ((const float4*)(g_bufB + (size_t)s0 * DD))[lane];
            acc0.x += v0.x; acc0.y += v0.y; acc0.z += v0.z; acc0.w += v0.w;
        }
        acc0.x += acc1.x + acc2.x + acc3.x;
        acc0.y += acc1.y + acc2.y + acc3.y;
        acc0.z += acc1.z + acc2.z + acc3.z;
        acc0.w += acc1.w + acc2.w + acc3.w;

        float nd = g_norm_dst[node];
        float4 b4 = ((const float4*)bg)[lane];
        float4 r = ((const float4*)(g_bufR + (size_t)node * DD))[lane];
        y.x = fmaxf(fmaf(acc0.x, nd, b4.x), 0.f) + r.x;
        y.y = fmaxf(fmaf(acc0.y, nd, b4.y), 0.f) + r.y;
        y.z = fmaxf(fmaf(acc0.z, nd, b4.z), 0.f) + r.z;
        y.w = fmaxf(fmaf(acc0.w, nd, b4.w), 0.f) + r.w;
        ((float4*)(g_bufA + (size_t)node * DD))[lane] = y;
    }
    // per-warp partials (stores, not atomics)
    ((float4*)&ssum[w][0])[lane] = y;
    float4 y2 = make_float4(y.x * y.x, y.y * y.y, y.z * y.z, y.w * y.w);
    ((float4*)&ssq[w][0])[lane] = y2;
    __syncthreads();
    if (tid < DD) {
        float s = 0.f;
#pragma unroll
        for (int i = 0; i < 8; i++) s += ssum[i][tid];
        atomicAdd(&g_stats[tid], s);
    } else {
        int j = tid - DD;
        float s = 0.f;
#pragma unroll
        for (int i = 0; i < 8; i++) s += ssq[i][j];
        atomicAdd(&g_stats[DD + j], s);
    }
}

// ---------------- BN prep: cs = gamma*iv, cb = beta - mu*cs; reset stats ----------------
__global__ void k_bnprep(const float* __restrict__ gamma, const float* __restrict__ beta) {
    int j = threadIdx.x;
    float invN = 1.0f / (float)NN;
    float mu = g_stats[j] * invN;
    float var = fmaxf(g_stats[DD + j] * invN - mu * mu, 0.f);
    float s = gamma[j] * rsqrtf(var + BN_EPS);
    g_cs[j] = s;
    g_cb[j] = beta[j] - mu * s;
    g_stats[j] = 0.f;
    g_stats[DD + j] = 0.f;
}

// ---------------- pooling (BN affine applied here) + counts ----------------
__global__ void k_pool(const int* __restrict__ gid, const int* __restrict__ mid) {
    int g = blockIdx.x * blockDim.x + threadIdx.x;
    int node = g >> 5;
    int lane = threadIdx.x & 31;
    if (node >= NN) return;
    float4 v = ((const float4*)(g_bufA + (size_t)node * DD))[lane];
    float4 s4 = ((const float4*)g_cs)[lane];
    float4 h4 = ((const float4*)g_cb)[lane];
    v.x = fmaf(v.x, s4.x, h4.x);
    v.y = fmaf(v.y, s4.y, h4.y);
    v.z = fmaf(v.z, s4.z, h4.z);
    v.w = fmaf(v.w, s4.w, h4.w);
    int gi = gid[node], mi = mid[node];
    atomicAdd(((float4*)(g_gsum + (size_t)gi * DD)) + lane, v);
    atomicAdd(((float4*)(g_msum + (size_t)mi * DD)) + lane, v);
    if (lane == 0) {
        atomicAdd(&g_gcnt[gi], 1.0f);
        atomicAdd(&g_mcnt[mi], 1.0f);
    }
}

__global__ void k_finalize(float* __restrict__ out_gf) {
    int idx = blockIdx.x * blockDim.x + threadIdx.x;  // (G+M)*D
    if (idx >= (GG + MM) * DD) return;
    int row = idx / DD, j = idx % DD;
    float v;
    if (row < GG) {
        v = g_gsum[row * DD + j] / fmaxf(g_gcnt[row], 1.0f);
        out_gf[row * DD + j] = v;
    } else {
        int mrow = row - GG + 1;  // drop motif segment 0
        v = g_msum[mrow * DD + j] / fmaxf(g_mcnt[mrow], 1.0f);
    }
    g_headin[idx] = v;
}

// ---------------- fp32 tiled GEMM with f32x2 (head MLP) ----------------
__global__ void k_gemm(const float* __restrict__ X, const float* __restrict__ W,
                       const float* __restrict__ bias,
                       float* __restrict__ Y, int nrows, int K, int ncols, int do_relu) {
    extern __shared__ float sm[];
    float* Ws = sm;               // 128*128
    float* Xs = sm + 128 * 128;   // 64*128
    const int tid = threadIdx.x;
    const int tx = tid & 31;
    const int ty = tid >> 5;
    const int r0 = blockIdx.x * 64;
    const int c0 = blockIdx.y * 128;

    unsigned long long acc[8][2];
#pragma unroll
    for (int m = 0; m < 8; m++) acc[m][0] = acc[m][1] = 0ull;

    for (int kb = 0; kb < K; kb += 128) {
#pragma unroll
        for (int i = 0; i < 16; i++) {
            int f = tid + 256 * i;
            int r = f >> 5, c4 = f & 31;
            ((float4*)Ws)[f] = *(const float4*)&W[(size_t)(kb + r) * ncols + c0 + c4 * 4];
        }
#pragma unroll
        for (int i = 0; i < 8; i++) {
            int f = tid + 256 * i;
            int m = f >> 5, k4 = f & 31;
            int row = r0 + m;
            float4 v = make_float4(0.f, 0.f, 0.f, 0.f);
            if (row < nrows) v = *(const float4*)&X[(size_t)row * K + kb + k4 * 4];
            ((float4*)Xs)[f] = v;
        }
        __syncthreads();

#pragma unroll 2
        for (int k = 0; k < 128; k += 4) {
            float4 xv[8];
#pragma unroll
            for (int m = 0; m < 8; m++)
                xv[m] = *(const float4*)&Xs[(ty * 8 + m) * 128 + k];
#pragma unroll
            for (int kk = 0; kk < 4; kk++) {
                ulonglong2 w = *(const ulonglong2*)&Ws[(k + kk) * 128 + tx * 4];
#pragma unroll
                for (int m = 0; m < 8; m++) {
                    float x = (kk == 0) ? xv[m].x : (kk == 1) ? xv[m].y
                            : (kk == 2) ? xv[m].z : xv[m].w;
                    unsigned long long xp = pack_dup(x);
                    ffma2(acc[m][0], xp, w.x);
                    ffma2(acc[m][1], xp, w.y);
                }
            }
        }
        __syncthreads();
    }

    float4 b4 = make_float4(0.f, 0.f, 0.f, 0.f);
    if (bias) b4 = *(const float4*)&bias[c0 + tx * 4];
#pragma unroll
    for (int m = 0; m < 8; m++) {
        int row = r0 + ty * 8 + m;
        if (row < nrows) {
            float2 p0 = unpack2(acc[m][0]);
            float2 p1 = unpack2(acc[m][1]);
            float4 o;
            o.x = p0.x + b4.x; o.y = p0.y + b4.y;
            o.z = p1.x + b4.z; o.w = p1.y + b4.w;
            if (do_relu) {
                o.x = fmaxf(o.x, 0.f); o.y = fmaxf(o.y, 0.f);
                o.z = fmaxf(o.z, 0.f); o.w = fmaxf(o.w, 0.f);
            }
            *(float4*)&Y[(size_t)row * ncols + c0 + tx * 4] = o;
        }
    }
}

// ---------------- launch ----------------
extern "C" void kernel_launch(void* const* d_in, const int* in_sizes, int n_in,
                              void* d_out, int out_size) {
    const float* node_feats = (const float*)d_in[0];
    const int*   src        = (const int*)d_in[1];
    const int*   dst        = (const int*)d_in[2];
    const int*   gid        = (const int*)d_in[3];
    const int*   mid        = (const int*)d_in[4];
    const float* Wg         = (const float*)d_in[5];
    const float* bg         = (const float*)d_in[6];
    const float* Wr         = (const float*)d_in[7];
    const float* br         = (const float*)d_in[8];
    const float* gamma      = (const float*)d_in[9];
    const float* beta       = (const float*)d_in[10];
    const float* W_feat     = (const float*)d_in[11];
    const float* b_feat     = (const float*)d_in[12];
    const float* W1         = (const float*)d_in[13];
    const float* b1         = (const float*)d_in[14];
    const float* W2         = (const float*)d_in[15];
    const float* b2         = (const float*)d_in[16];
    float* out = (float*)d_out;

    void *pA, *pdi, *pdo, *pns, *pcs, *pcb, *phin, *ph1, *ph2, *pB, *pR;
    cudaGetSymbolAddress(&pA, g_bufA);
    cudaGetSymbolAddress(&pB, g_bufB);
    cudaGetSymbolAddress(&pR, g_bufR);
    cudaGetSymbolAddress(&pdi, g_degin);
    cudaGetSymbolAddress(&pdo, g_degout);
    cudaGetSymbolAddress(&pns, g_norm_src);
    cudaGetSymbolAddress(&pcs, g_cs);
    cudaGetSymbolAddress(&pcb, g_cb);
    cudaGetSymbolAddress(&phin, g_headin);
    cudaGetSymbolAddress(&ph1, g_head1);
    cudaGetSymbolAddress(&ph2, g_head2);

    const int SMEM_G = (128 * 128 + 64 * 128) * 4;               // 96 KB
    const int SMEM_D = (64 * 128 + 2 * 128 * 128) * 4;           // 160 KB
    cudaFuncSetAttribute(k_gemm, cudaFuncAttributeMaxDynamicSharedMemorySize, SMEM_G);
    cudaFuncSetAttribute(k_dualgemm, cudaFuncAttributeMaxDynamicSharedMemorySize, SMEM_D);

    // ---- CSR build + norms (cursor zeroed in k_scan, stats in k_norms) ----
    cudaMemsetAsync(pdi, 0, NN * sizeof(int));
    cudaMemsetAsync(pdo, 0, NN * sizeof(int));
    k_hist<<<(EE + 255) / 256, 256>>>(src, dst);
    k_norms<<<(NN + 255) / 256, 256>>>();
    k_scan<<<1, 1024>>>();
    k_place<<<(EE + 255) / 256, 256>>>(src, dst);

    const int gemm_blocks = (NN + 63) / 64;   // 782
    const int agg_blocks = (NN + 7) / 8;      // 6250

    for (int l = 0; l < LL; l++) {
        const float* hin = (l == 0) ? node_feats : (const float*)pA;

        // B = norm_src .* (Xn @ Wg[l]);  R = relu(Xn @ Wr[l] + br[l])
        k_dualgemm<<<gemm_blocks, 256, SMEM_D>>>(
            hin, Wg + (size_t)l * DD * DD, Wr + (size_t)l * DD * DD,
            br + (size_t)l * DD, (const float*)pns,
            (l == 0) ? nullptr : (const float*)pcs,
            (l == 0) ? nullptr : (const float*)pcb,
            (float*)pB, (float*)pR, NN);

        // A = relu(agg*nd + bg) + R; BN stats accumulated; layer 2 zeroes pool bufs
        k_agg<<<agg_blocks, 256>>>(bg + (size_t)l * DD, (l == LL - 1) ? 1 : 0);

        // fold BN into affine cs/cb for next consumer; resets stats
        k_bnprep<<<1, DD>>>(gamma + (size_t)l * DD, beta + (size_t)l * DD);
    }

    // ---- pooling (applies layer-2 BN affine) ----
    k_pool<<<(NN * 32 + 255) / 256, 256>>>(gid, mid);
    k_finalize<<<((GG + MM) * DD + 255) / 256, 256>>>(out);

    // ---- head MLP on [graph_feats ; h_sub] = 2560 rows ----
    const int HR = GG + MM;
    const int hblocks = (HR + 63) / 64;  // 40
    k_gemm<<<dim3(hblocks, FFN / 128), 256, SMEM_G>>>(
        (const float*)phin, W_feat, b_feat, (float*)ph1, HR, DD, FFN, 0);
    k_gemm<<<dim3(hblocks, FFN / 128), 256, SMEM_G>>>(
        (const float*)ph1, W1, b1, (float*)ph2, HR, FFN, FFN, 1);
    k_gemm<<<dim3(hblocks, 1), 256, SMEM_G>>>(
        (const float*)ph2, W2, b2, out + (size_t)GG * DD, HR, FFN, DD, 0);
}

// round 5
// speedup vs baseline: 1.2298x; 1.0533x over previous
#include <cuda_runtime.h>
#include <cuda_bf16.h>
#include <cstddef>

#define NN 50000
#define EE 600000
#define GG 512
#define MM 2048
#define DD 128
#define FFN 256
#define LL 3
#define BN_EPS 1e-5f

// ---------------- scratch (device globals) ----------------
__device__ float g_bufA[NN * DD];   // layer output h
__device__ float g_bufB[NN * DD];   // hw branch
__device__ float g_bufR[NN * DD];   // residual branch
__device__ int   g_degin[NN];
__device__ int   g_degout[NN];
__device__ int   g_cursor[NN];
__device__ int   g_rowstart[NN + 1];
__device__ int   g_csr_src[EE];
__device__ float g_norm_src[NN];
__device__ float g_norm_dst[NN];
__device__ float g_stats[2 * DD];
__device__ float g_cs[DD];
__device__ float g_cb[DD];
__device__ float g_gsum[GG * DD];
__device__ float g_gcnt[GG];
__device__ float g_msum[(MM + 1) * DD];
__device__ float g_mcnt[MM + 1];
__device__ float g_headin[(GG + MM) * DD];
__device__ float g_head1[(GG + MM) * FFN];
__device__ float g_head2[(GG + MM) * FFN];

// ---------------- f32x2 helpers ----------------
__device__ __forceinline__ unsigned long long pack_dup(float x) {
    unsigned long long p;
    unsigned int xb = __float_as_uint(x);
    asm("mov.b64 %0, {%1, %1};" : "=l"(p) : "r"(xb));
    return p;
}
__device__ __forceinline__ void ffma2(unsigned long long& acc, unsigned long long a,
                                      unsigned long long b) {
    asm("fma.rn.f32x2 %0, %1, %2, %0;" : "+l"(acc) : "l"(a), "l"(b));
}
__device__ __forceinline__ float2 unpack2(unsigned long long a) {
    float lo, hi;
    asm("mov.b64 {%0, %1}, %2;" : "=f"(lo), "=f"(hi) : "l"(a));
    return make_float2(lo, hi);
}

// ---------------- setup ----------------
__global__ void k_zero() {
    int i = blockIdx.x * blockDim.x + threadIdx.x;
    if (i < NN) { g_degin[i] = 0; g_degout[i] = 0; }
}

__global__ void k_hist(const int* __restrict__ src, const int* __restrict__ dst) {
    int e = blockIdx.x * blockDim.x + threadIdx.x;
    if (e < EE) {
        atomicAdd(&g_degout[src[e]], 1);
        atomicAdd(&g_degin[dst[e]], 1);
    }
}

__global__ void k_norms() {
    int i = blockIdx.x * blockDim.x + threadIdx.x;
    if (i < NN) {
        g_norm_src[i] = rsqrtf(fmaxf((float)g_degout[i], 1.0f));
        g_norm_dst[i] = rsqrtf(fmaxf((float)g_degin[i], 1.0f));
    }
    if (i < 2 * DD) g_stats[i] = 0.f;   // zero BN stats for layer 0
}

// single-block exclusive scan of g_degin -> g_rowstart (also zeroes g_cursor)
__global__ void k_scan() {
    const int T = 1024;
    __shared__ int buf[T];
    int tid = threadIdx.x;
    const int chunk = (NN + T - 1) / T;
    int base = tid * chunk;
    int s = 0;
    for (int i = 0; i < chunk; i++) {
        int idx = base + i;
        if (idx < NN) { s += g_degin[idx]; g_cursor[idx] = 0; }
    }
    buf[tid] = s;
    __syncthreads();
    for (int off = 1; off < T; off <<= 1) {
        int t = (tid >= off) ? buf[tid - off] : 0;
        __syncthreads();
        buf[tid] += t;
        __syncthreads();
    }
    int running = buf[tid] - s;
    for (int i = 0; i < chunk; i++) {
        int idx = base + i;
        if (idx < NN) {
            g_rowstart[idx] = running;
            running += g_degin[idx];
        }
    }
    if (tid == 0) g_rowstart[NN] = EE;
}

__global__ void k_place(const int* __restrict__ src, const int* __restrict__ dst) {
    int e = blockIdx.x * blockDim.x + threadIdx.x;
    if (e < EE) {
        int d = dst[e];
        int slot = atomicAdd(&g_cursor[d], 1);
        g_csr_src[g_rowstart[d] + slot] = src[e];
    }
}

// ---------------- fused dual GEMM (fp32 FFMA2), 64x64 dual-output tile, 2 CTAs/SM ----------------
// Y1 = rs .* (Xn @ W1)      Xn = X*cs + cb (identity if cs==nullptr)
// Y2 = relu(Xn @ W2 + b2)
// grid.x tiles 64 rows, grid.y tiles 64 of the 128 columns.
__global__ void __launch_bounds__(256, 2)
k_dualgemm(const float* __restrict__ X,
           const float* __restrict__ W1,
           const float* __restrict__ W2,
           const float* __restrict__ b2,
           const float* __restrict__ rs,
           const float* __restrict__ cs,
           const float* __restrict__ cb,
           float* __restrict__ Y1, float* __restrict__ Y2,
           int nrows) {
    extern __shared__ float sm[];
    float* Xs  = sm;               // 64*128  (32 KB)
    float* W1s = sm + 64 * 128;    // 128*64  (32 KB)
    float* W2s = W1s + 128 * 64;   // 128*64  (32 KB)
    const int tid = threadIdx.x;
    const int tx = tid & 15;       // 16 col-groups of 4 cols (64 cols)
    const int ty = tid >> 4;       // 16 row-groups of 4 rows (64 rows)
    const int r0 = blockIdx.x * 64;
    const int c0 = blockIdx.y * 64;

    // W halves: 128 rows x 16 float4 = 2048 float4 each; 8 per thread
#pragma unroll
    for (int i = 0; i < 8; i++) {
        int f = tid + 256 * i;
        int r = f >> 4, c4 = f & 15;
        W1s[0] = W1s[0];  // no-op to keep layout obvious
        ((float4*)W1s)[f] = ((const float4*)&W1[(size_t)r * DD + c0])[c4];
        ((float4*)W2s)[f] = ((const float4*)&W2[(size_t)r * DD + c0])[c4];
    }
    // X tile 64x128 = 2048 float4; 8 per thread; BN affine folded in
#pragma unroll
    for (int i = 0; i < 8; i++) {
        int f = tid + 256 * i;
        int row = r0 + (f >> 5);
        int j4 = f & 31;
        float4 v = make_float4(0.f, 0.f, 0.f, 0.f);
        if (row < nrows) {
            v = ((const float4*)(X + (size_t)row * DD))[j4];
            if (cs) {
                float4 s4 = ((const float4*)cs)[j4];
                float4 h4 = ((const float4*)cb)[j4];
                v.x = fmaf(v.x, s4.x, h4.x);
                v.y = fmaf(v.y, s4.y, h4.y);
                v.z = fmaf(v.z, s4.z, h4.z);
                v.w = fmaf(v.w, s4.w, h4.w);
            }
        }
        ((float4*)Xs)[f] = v;
    }
    __syncthreads();

    // acc: 4 rows x 4 cols x 2 matrices
    unsigned long long a1[4][2], a2[4][2];
#pragma unroll
    for (int m = 0; m < 4; m++) {
        a1[m][0] = a1[m][1] = 0ull;
        a2[m][0] = a2[m][1] = 0ull;
    }

#pragma unroll 4
    for (int k = 0; k < 128; k += 4) {
        float4 xv[4];
#pragma unroll
        for (int m = 0; m < 4; m++)
            xv[m] = *(const float4*)&Xs[(ty * 4 + m) * 128 + k];
#pragma unroll
        for (int kk = 0; kk < 4; kk++) {
            ulonglong2 w1 = *(const ulonglong2*)&W1s[(k + kk) * 64 + tx * 4];
            ulonglong2 w2 = *(const ulonglong2*)&W2s[(k + kk) * 64 + tx * 4];
#pragma unroll
            for (int m = 0; m < 4; m++) {
                float x = (kk == 0) ? xv[m].x : (kk == 1) ? xv[m].y
                        : (kk == 2) ? xv[m].z : xv[m].w;
                unsigned long long xp = pack_dup(x);
                ffma2(a1[m][0], xp, w1.x);
                ffma2(a1[m][1], xp, w1.y);
                ffma2(a2[m][0], xp, w2.x);
                ffma2(a2[m][1], xp, w2.y);
            }
        }
    }

    float4 b4 = ((const float4*)&b2[c0])[tx];
#pragma unroll
    for (int m = 0; m < 4; m++) {
        int row = r0 + ty * 4 + m;
        if (row < nrows) {
            float s = rs[row];
            float2 p0 = unpack2(a1[m][0]);
            float2 p1 = unpack2(a1[m][1]);
            float4 o1 = make_float4(p0.x * s, p0.y * s, p1.x * s, p1.y * s);
            ((float4*)(Y1 + (size_t)row * DD + c0))[tx] = o1;
            float2 q0 = unpack2(a2[m][0]);
            float2 q1 = unpack2(a2[m][1]);
            float4 o2;
            o2.x = fmaxf(q0.x + b4.x, 0.f);
            o2.y = fmaxf(q0.y + b4.y, 0.f);
            o2.z = fmaxf(q1.x + b4.z, 0.f);
            o2.w = fmaxf(q1.y + b4.w, 0.f);
            ((float4*)(Y2 + (size_t)row * DD + c0))[tx] = o2;
        }
    }
}

// ---------------- CSR aggregation + combine + BN stats (fused) ----------------
__global__ void k_agg(const float* __restrict__ bg, int zpool) {
    __shared__ float ssum[8][DD];
    __shared__ float ssq[8][DD];
    int tid = threadIdx.x;
    int w = tid >> 5;
    int lane = tid & 31;

    if (zpool) {
        int gstep = gridDim.x * blockDim.x;
        int gidx = blockIdx.x * blockDim.x + tid;
        for (int i = gidx; i < GG * DD; i += gstep) g_gsum[i] = 0.f;
        for (int i = gidx; i < (MM + 1) * DD; i += gstep) g_msum[i] = 0.f;
        for (int i = gidx; i < GG; i += gstep) g_gcnt[i] = 0.f;
        for (int i = gidx; i < MM + 1; i += gstep) g_mcnt[i] = 0.f;
    }

    int node = blockIdx.x * 8 + w;
    float4 y = make_float4(0.f, 0.f, 0.f, 0.f);
    if (node < NN) {
        int e0 = g_rowstart[node], e1 = g_rowstart[node + 1];
        float4 acc0 = make_float4(0.f, 0.f, 0.f, 0.f);
        float4 acc1 = make_float4(0.f, 0.f, 0.f, 0.f);
        float4 acc2 = make_float4(0.f, 0.f, 0.f, 0.f);
        float4 acc3 = make_float4(0.f, 0.f, 0.f, 0.f);
        int e = e0;
        for (; e + 4 <= e1; e += 4) {
            int s0 = g_csr_src[e], s1 = g_csr_src[e + 1];
            int s2 = g_csr_src[e + 2], s3 = g_csr_src[e + 3];
            float4 v0 = ((const float4*)(g_bufB + (size_t)s0 * DD))[lane];
            float4 v1 = ((const float4*)(g_bufB + (size_t)s1 * DD))[lane];
            float4 v2 = ((const float4*)(g_bufB + (size_t)s2 * DD))[lane];
            float4 v3 = ((const float4*)(g_bufB + (size_t)s3 * DD))[lane];
            acc0.x += v0.x; acc0.y += v0.y; acc0.z += v0.z; acc0.w += v0.w;
            acc1.x += v1.x; acc1.y += v1.y; acc1.z += v1.z; acc1.w += v1.w;
            acc2.x += v2.x; acc2.y += v2.y; acc2.z += v2.z; acc2.w += v2.w;
            acc3.x += v3.x; acc3.y += v3.y; acc3.z += v3.z; acc3.w += v3.w;
        }
        for (; e < e1; e++) {
            int s0 = g_csr_src[e];
            float4 v0 = ((const float4*)(g_bufB + (size_t)s0 * DD))[lane];
            acc0.x += v0.x; acc0.y += v0.y; acc0.z += v0.z; acc0.w += v0.w;
        }
        acc0.x += acc1.x + acc2.x + acc3.x;
        acc0.y += acc1.y + acc2.y + acc3.y;
        acc0.z += acc1.z + acc2.z + acc3.z;
        acc0.w += acc1.w + acc2.w + acc3.w;

        float nd = g_norm_dst[node];
        float4 b4 = ((const float4*)bg)[lane];
        float4 r = ((const float4*)(g_bufR + (size_t)node * DD))[lane];
        y.x = fmaxf(fmaf(acc0.x, nd, b4.x), 0.f) + r.x;
        y.y = fmaxf(fmaf(acc0.y, nd, b4.y), 0.f) + r.y;
        y.z = fmaxf(fmaf(acc0.z, nd, b4.z), 0.f) + r.z;
        y.w = fmaxf(fmaf(acc0.w, nd, b4.w), 0.f) + r.w;
        ((float4*)(g_bufA + (size_t)node * DD))[lane] = y;
    }
    ((float4*)&ssum[w][0])[lane] = y;
    float4 y2 = make_float4(y.x * y.x, y.y * y.y, y.z * y.z, y.w * y.w);
    ((float4*)&ssq[w][0])[lane] = y2;
    __syncthreads();
    if (tid < DD) {
        float s = 0.f;
#pragma unroll
        for (int i = 0; i < 8; i++) s += ssum[i][tid];
        atomicAdd(&g_stats[tid], s);
    } else {
        int j = tid - DD;
        float s = 0.f;
#pragma unroll
        for (int i = 0; i < 8; i++) s += ssq[i][j];
        atomicAdd(&g_stats[DD + j], s);
    }
}

// ---------------- BN prep ----------------
__global__ void k_bnprep(const float* __restrict__ gamma, const float* __restrict__ beta) {
    int j = threadIdx.x;
    float invN = 1.0f / (float)NN;
    float mu = g_stats[j] * invN;
    float var = fmaxf(g_stats[DD + j] * invN - mu * mu, 0.f);
    float s = gamma[j] * rsqrtf(var + BN_EPS);
    g_cs[j] = s;
    g_cb[j] = beta[j] - mu * s;
    g_stats[j] = 0.f;
    g_stats[DD + j] = 0.f;
}

// ---------------- pooling (BN affine applied here) + counts ----------------
__global__ void k_pool(const int* __restrict__ gid, const int* __restrict__ mid) {
    int g = blockIdx.x * blockDim.x + threadIdx.x;
    int node = g >> 5;
    int lane = threadIdx.x & 31;
    if (node >= NN) return;
    float4 v = ((const float4*)(g_bufA + (size_t)node * DD))[lane];
    float4 s4 = ((const float4*)g_cs)[lane];
    float4 h4 = ((const float4*)g_cb)[lane];
    v.x = fmaf(v.x, s4.x, h4.x);
    v.y = fmaf(v.y, s4.y, h4.y);
    v.z = fmaf(v.z, s4.z, h4.z);
    v.w = fmaf(v.w, s4.w, h4.w);
    int gi = gid[node], mi = mid[node];
    atomicAdd(((float4*)(g_gsum + (size_t)gi * DD)) + lane, v);
    atomicAdd(((float4*)(g_msum + (size_t)mi * DD)) + lane, v);
    if (lane == 0) {
        atomicAdd(&g_gcnt[gi], 1.0f);
        atomicAdd(&g_mcnt[mi], 1.0f);
    }
}

__global__ void k_finalize(float* __restrict__ out_gf) {
    int idx = blockIdx.x * blockDim.x + threadIdx.x;
    if (idx >= (GG + MM) * DD) return;
    int row = idx / DD, j = idx % DD;
    float v;
    if (row < GG) {
        v = g_gsum[row * DD + j] / fmaxf(g_gcnt[row], 1.0f);
        out_gf[row * DD + j] = v;
    } else {
        int mrow = row - GG + 1;  // drop motif segment 0
        v = g_msum[mrow * DD + j] / fmaxf(g_mcnt[mrow], 1.0f);
    }
    g_headin[idx] = v;
}

// ---------------- fp32 tiled GEMM with f32x2 (head MLP) ----------------
__global__ void k_gemm(const float* __restrict__ X, const float* __restrict__ W,
                       const float* __restrict__ bias,
                       float* __restrict__ Y, int nrows, int K, int ncols, int do_relu) {
    extern __shared__ float sm[];
    float* Ws = sm;               // 128*128
    float* Xs = sm + 128 * 128;   // 64*128
    const int tid = threadIdx.x;
    const int tx = tid & 31;
    const int ty = tid >> 5;
    const int r0 = blockIdx.x * 64;
    const int c0 = blockIdx.y * 128;

    unsigned long long acc[8][2];
#pragma unroll
    for (int m = 0; m < 8; m++) acc[m][0] = acc[m][1] = 0ull;

    for (int kb = 0; kb < K; kb += 128) {
#pragma unroll
        for (int i = 0; i < 16; i++) {
            int f = tid + 256 * i;
            int r = f >> 5, c4 = f & 31;
            ((float4*)Ws)[f] = *(const float4*)&W[(size_t)(kb + r) * ncols + c0 + c4 * 4];
        }
#pragma unroll
        for (int i = 0; i < 8; i++) {
            int f = tid + 256 * i;
            int m = f >> 5, k4 = f & 31;
            int row = r0 + m;
            float4 v = make_float4(0.f, 0.f, 0.f, 0.f);
            if (row < nrows) v = *(const float4*)&X[(size_t)row * K + kb + k4 * 4];
            ((float4*)Xs)[f] = v;
        }
        __syncthreads();

#pragma unroll 2
        for (int k = 0; k < 128; k += 4) {
            float4 xv[8];
#pragma unroll
            for (int m = 0; m < 8; m++)
                xv[m] = *(const float4*)&Xs[(ty * 8 + m) * 128 + k];
#pragma unroll
            for (int kk = 0; kk < 4; kk++) {
                ulonglong2 w = *(const ulonglong2*)&Ws[(k + kk) * 128 + tx * 4];
#pragma unroll
                for (int m = 0; m < 8; m++) {
                    float x = (kk == 0) ? xv[m].x : (kk == 1) ? xv[m].y
                            : (kk == 2) ? xv[m].z : xv[m].w;
                    unsigned long long xp = pack_dup(x);
                    ffma2(acc[m][0], xp, w.x);
                    ffma2(acc[m][1], xp, w.y);
                }
            }
        }
        __syncthreads();
    }

    float4 b4 = make_float4(0.f, 0.f, 0.f, 0.f);
    if (bias) b4 = *(const float4*)&bias[c0 + tx * 4];
#pragma unroll
    for (int m = 0; m < 8; m++) {
        int row = r0 + ty * 8 + m;
        if (row < nrows) {
            float2 p0 = unpack2(acc[m][0]);
            float2 p1 = unpack2(acc[m][1]);
            float4 o;
            o.x = p0.x + b4.x; o.y = p0.y + b4.y;
            o.z = p1.x + b4.z; o.w = p1.y + b4.w;
            if (do_relu) {
                o.x = fmaxf(o.x, 0.f); o.y = fmaxf(o.y, 0.f);
                o.z = fmaxf(o.z, 0.f); o.w = fmaxf(o.w, 0.f);
            }
            *(float4*)&Y[(size_t)row * ncols + c0 + tx * 4] = o;
        }
    }
}

// ---------------- launch ----------------
extern "C" void kernel_launch(void* const* d_in, const int* in_sizes, int n_in,
                              void* d_out, int out_size) {
    const float* node_feats = (const float*)d_in[0];
    const int*   src        = (const int*)d_in[1];
    const int*   dst        = (const int*)d_in[2];
    const int*   gid        = (const int*)d_in[3];
    const int*   mid        = (const int*)d_in[4];
    const float* Wg         = (const float*)d_in[5];
    const float* bg         = (const float*)d_in[6];
    const float* Wr         = (const float*)d_in[7];
    const float* br         = (const float*)d_in[8];
    const float* gamma      = (const float*)d_in[9];
    const float* beta       = (const float*)d_in[10];
    const float* W_feat     = (const float*)d_in[11];
    const float* b_feat     = (const float*)d_in[12];
    const float* W1         = (const float*)d_in[13];
    const float* b1         = (const float*)d_in[14];
    const float* W2         = (const float*)d_in[15];
    const float* b2         = (const float*)d_in[16];
    float* out = (float*)d_out;

    void *pA, *pns, *pcs, *pcb, *phin, *ph1, *ph2, *pB, *pR;
    cudaGetSymbolAddress(&pA, g_bufA);
    cudaGetSymbolAddress(&pB, g_bufB);
    cudaGetSymbolAddress(&pR, g_bufR);
    cudaGetSymbolAddress(&pns, g_norm_src);
    cudaGetSymbolAddress(&pcs, g_cs);
    cudaGetSymbolAddress(&pcb, g_cb);
    cudaGetSymbolAddress(&phin, g_headin);
    cudaGetSymbolAddress(&ph1, g_head1);
    cudaGetSymbolAddress(&ph2, g_head2);

    const int SMEM_G = (128 * 128 + 64 * 128) * 4;            // 96 KB (head gemm)
    const int SMEM_D = (64 * 128 + 2 * 128 * 64) * 4;         // 96 KB (dual gemm, 2 CTAs/SM)
    cudaFuncSetAttribute(k_gemm, cudaFuncAttributeMaxDynamicSharedMemorySize, SMEM_G);
    cudaFuncSetAttribute(k_dualgemm, cudaFuncAttributeMaxDynamicSharedMemorySize, SMEM_D);

    // ---- CSR build + norms (5 launches before first dualgemm => ncu -s 5 captures it) ----
    k_zero<<<(NN + 255) / 256, 256>>>();
    k_hist<<<(EE + 255) / 256, 256>>>(src, dst);
    k_norms<<<(NN + 255) / 256, 256>>>();
    k_scan<<<1, 1024>>>();
    k_place<<<(EE + 255) / 256, 256>>>(src, dst);

    const int gemm_rows = (NN + 63) / 64;     // 782
    const int agg_blocks = (NN + 7) / 8;      // 6250

    for (int l = 0; l < LL; l++) {
        const float* hin = (l == 0) ? node_feats : (const float*)pA;

        // B = norm_src .* (Xn @ Wg[l]);  R = relu(Xn @ Wr[l] + br[l])
        k_dualgemm<<<dim3(gemm_rows, 2), 256, SMEM_D>>>(
            hin, Wg + (size_t)l * DD * DD, Wr + (size_t)l * DD * DD,
            br + (size_t)l * DD, (const float*)pns,
            (l == 0) ? nullptr : (const float*)pcs,
            (l == 0) ? nullptr : (const float*)pcb,
            (float*)pB, (float*)pR, NN);

        // A = relu(agg*nd + bg) + R; BN stats accumulated; layer 2 zeroes pool bufs
        k_agg<<<agg_blocks, 256>>>(bg + (size_t)l * DD, (l == LL - 1) ? 1 : 0);

        // fold BN into affine cs/cb for next consumer; resets stats
        k_bnprep<<<1, DD>>>(gamma + (size_t)l * DD, beta + (size_t)l * DD);
    }

    // ---- pooling (applies layer-2 BN affine) ----
    k_pool<<<(NN * 32 + 255) / 256, 256>>>(gid, mid);
    k_finalize<<<((GG + MM) * DD + 255) / 256, 256>>>(out);

    // ---- head MLP on [graph_feats ; h_sub] = 2560 rows ----
    const int HR = GG + MM;
    const int hblocks = (HR + 63) / 64;  // 40
    k_gemm<<<dim3(hblocks, FFN / 128), 256, SMEM_G>>>(
        (const float*)phin, W_feat, b_feat, (float*)ph1, HR, DD, FFN, 0);
    k_gemm<<<dim3(hblocks, FFN / 128), 256, SMEM_G>>>(
        (const float*)ph1, W1, b1, (float*)ph2, HR, FFN, FFN, 1);
    k_gemm<<<dim3(hblocks, 1), 256, SMEM_G>>>(
        (const float*)ph2, W2, b2, out + (size_t)GG * DD, HR, FFN, DD, 0);
}

// round 6
// speedup vs baseline: 1.3871x; 1.1280x over previous
#include <cuda_runtime.h>
#include <cuda_bf16.h>
#include <cstddef>

#define NN 50000
#define EE 600000
#define GG 512
#define MM 2048
#define DD 128
#define FFN 256
#define LL 3
#define BN_EPS 1e-5f
#define SCAN_B 196   // ceil(NN/256)

// ---------------- scratch (device globals) ----------------
__device__ float g_bufA[NN * DD];   // layer output h
__device__ float g_bufB[NN * DD];   // hw branch
__device__ float g_bufR[NN * DD];   // residual branch
__device__ int   g_degin[NN];
__device__ int   g_degout[NN];
__device__ int   g_cursor[NN];
__device__ int   g_rowstart[NN + 1];
__device__ int   g_csr_src[EE];
__device__ int   g_bsum[SCAN_B];
__device__ int   g_boff[SCAN_B];
__device__ float g_norm_src[NN];
__device__ float g_norm_dst[NN];
__device__ float g_stats[2 * DD];
__device__ float g_cs[DD];
__device__ float g_cb[DD];
__device__ float g_gsum[GG * DD];
__device__ float g_gcnt[GG];
__device__ float g_msum[(MM + 1) * DD];
__device__ float g_mcnt[MM + 1];
__device__ float g_headin[(GG + MM) * DD];
__device__ float g_head1[(GG + MM) * FFN];
__device__ float g_head2[(GG + MM) * FFN];

// ---------------- f32x2 helpers ----------------
__device__ __forceinline__ unsigned long long pack_dup(float x) {
    unsigned long long p;
    unsigned int xb = __float_as_uint(x);
    asm("mov.b64 %0, {%1, %1};" : "=l"(p) : "r"(xb));
    return p;
}
__device__ __forceinline__ void ffma2(unsigned long long& acc, unsigned long long a,
                                      unsigned long long b) {
    asm("fma.rn.f32x2 %0, %1, %2, %0;" : "+l"(acc) : "l"(a), "l"(b));
}
__device__ __forceinline__ float2 unpack2(unsigned long long a) {
    float lo, hi;
    asm("mov.b64 {%0, %1}, %2;" : "=f"(lo), "=f"(hi) : "l"(a));
    return make_float2(lo, hi);
}

// ---------------- setup ----------------
__global__ void k_zero() {
    int i = blockIdx.x * blockDim.x + threadIdx.x;
    if (i < NN) { g_degin[i] = 0; g_degout[i] = 0; }
}

__global__ void k_hist(const int* __restrict__ src, const int* __restrict__ dst) {
    int e = blockIdx.x * blockDim.x + threadIdx.x;
    if (e < EE) {
        atomicAdd(&g_degout[src[e]], 1);
        atomicAdd(&g_degin[dst[e]], 1);
    }
}

__global__ void k_norms() {
    int i = blockIdx.x * blockDim.x + threadIdx.x;
    if (i < NN) {
        g_norm_src[i] = rsqrtf(fmaxf((float)g_degout[i], 1.0f));
        g_norm_dst[i] = rsqrtf(fmaxf((float)g_degin[i], 1.0f));
    }
    if (i < 2 * DD) g_stats[i] = 0.f;   // zero BN stats for layer 0
}

// ---------------- multi-block scan of g_degin -> g_rowstart ----------------
__global__ void k_scan1() {          // grid SCAN_B, block 256: block sums + zero cursor
    __shared__ int sh[256];
    int tid = threadIdx.x;
    int i = blockIdx.x * 256 + tid;
    int v = (i < NN) ? g_degin[i] : 0;
    if (i < NN) g_cursor[i] = 0;
    sh[tid] = v;
    __syncthreads();
    for (int off = 128; off > 0; off >>= 1) {
        if (tid < off) sh[tid] += sh[tid + off];
        __syncthreads();
    }
    if (tid == 0) g_bsum[blockIdx.x] = sh[0];
}

__global__ void k_scan2() {          // 1 block 256: exclusive scan of SCAN_B partials
    __shared__ int sh[256];
    int tid = threadIdx.x;
    int v = (tid < SCAN_B) ? g_bsum[tid] : 0;
    sh[tid] = v;
    __syncthreads();
    for (int off = 1; off < 256; off <<= 1) {
        int t = (tid >= off) ? sh[tid - off] : 0;
        __syncthreads();
        sh[tid] += t;
        __syncthreads();
    }
    if (tid < SCAN_B) g_boff[tid] = sh[tid] - v;
}

__global__ void k_scan3() {          // grid SCAN_B, block 256: local scan + offset
    __shared__ int sh[256];
    int tid = threadIdx.x;
    int i = blockIdx.x * 256 + tid;
    int v = (i < NN) ? g_degin[i] : 0;
    sh[tid] = v;
    __syncthreads();
    for (int off = 1; off < 256; off <<= 1) {
        int t = (tid >= off) ? sh[tid - off] : 0;
        __syncthreads();
        sh[tid] += t;
        __syncthreads();
    }
    if (i < NN) g_rowstart[i] = sh[tid] - v + g_boff[blockIdx.x];
    if (blockIdx.x == 0 && tid == 0) g_rowstart[NN] = EE;
}

__global__ void k_place(const int* __restrict__ src, const int* __restrict__ dst) {
    int e = blockIdx.x * blockDim.x + threadIdx.x;
    if (e < EE) {
        int d = dst[e];
        int slot = atomicAdd(&g_cursor[d], 1);
        g_csr_src[g_rowstart[d] + slot] = src[e];
    }
}

// ---------------- fused dual GEMM (fp32 FFMA2), 64x64 dual-output tile, 2 CTAs/SM ----------------
// Y1 = rs .* (Xn @ W1)      Xn = X*cs + cb (identity if cs==nullptr)
// Y2 = relu(Xn @ W2 + b2)
__global__ void __launch_bounds__(256, 2)
k_dualgemm(const float* __restrict__ X,
           const float* __restrict__ W1,
           const float* __restrict__ W2,
           const float* __restrict__ b2,
           const float* __restrict__ rs,
           const float* __restrict__ cs,
           const float* __restrict__ cb,
           float* __restrict__ Y1, float* __restrict__ Y2,
           int nrows) {
    extern __shared__ float sm[];
    float* Xs  = sm;               // 64*128  (32 KB)
    float* W1s = sm + 64 * 128;    // 128*64  (32 KB)
    float* W2s = W1s + 128 * 64;   // 128*64  (32 KB)
    const int tid = threadIdx.x;
    const int tx = tid & 15;       // 16 col-groups of 4 cols (64 cols)
    const int ty = tid >> 4;       // 16 row-groups of 4 rows (64 rows)
    const int r0 = blockIdx.x * 64;
    const int c0 = blockIdx.y * 64;

#pragma unroll
    for (int i = 0; i < 8; i++) {
        int f = tid + 256 * i;
        int r = f >> 4, c4 = f & 15;
        ((float4*)W1s)[f] = ((const float4*)&W1[(size_t)r * DD + c0])[c4];
        ((float4*)W2s)[f] = ((const float4*)&W2[(size_t)r * DD + c0])[c4];
    }
#pragma unroll
    for (int i = 0; i < 8; i++) {
        int f = tid + 256 * i;
        int row = r0 + (f >> 5);
        int j4 = f & 31;
        float4 v = make_float4(0.f, 0.f, 0.f, 0.f);
        if (row < nrows) {
            v = ((const float4*)(X + (size_t)row * DD))[j4];
            if (cs) {
                float4 s4 = ((const float4*)cs)[j4];
                float4 h4 = ((const float4*)cb)[j4];
                v.x = fmaf(v.x, s4.x, h4.x);
                v.y = fmaf(v.y, s4.y, h4.y);
                v.z = fmaf(v.z, s4.z, h4.z);
                v.w = fmaf(v.w, s4.w, h4.w);
            }
        }
        ((float4*)Xs)[f] = v;
    }
    __syncthreads();

    unsigned long long a1[4][2], a2[4][2];
#pragma unroll
    for (int m = 0; m < 4; m++) {
        a1[m][0] = a1[m][1] = 0ull;
        a2[m][0] = a2[m][1] = 0ull;
    }

#pragma unroll 4
    for (int k = 0; k < 128; k += 4) {
        float4 xv[4];
#pragma unroll
        for (int m = 0; m < 4; m++)
            xv[m] = *(const float4*)&Xs[(ty * 4 + m) * 128 + k];
#pragma unroll
        for (int kk = 0; kk < 4; kk++) {
            ulonglong2 w1 = *(const ulonglong2*)&W1s[(k + kk) * 64 + tx * 4];
            ulonglong2 w2 = *(const ulonglong2*)&W2s[(k + kk) * 64 + tx * 4];
#pragma unroll
            for (int m = 0; m < 4; m++) {
                float x = (kk == 0) ? xv[m].x : (kk == 1) ? xv[m].y
                        : (kk == 2) ? xv[m].z : xv[m].w;
                unsigned long long xp = pack_dup(x);
                ffma2(a1[m][0], xp, w1.x);
                ffma2(a1[m][1], xp, w1.y);
                ffma2(a2[m][0], xp, w2.x);
                ffma2(a2[m][1], xp, w2.y);
            }
        }
    }

    float4 b4 = ((const float4*)&b2[c0])[tx];
#pragma unroll
    for (int m = 0; m < 4; m++) {
        int row = r0 + ty * 4 + m;
        if (row < nrows) {
            float s = rs[row];
            float2 p0 = unpack2(a1[m][0]);
            float2 p1 = unpack2(a1[m][1]);
            float4 o1 = make_float4(p0.x * s, p0.y * s, p1.x * s, p1.y * s);
            ((float4*)(Y1 + (size_t)row * DD + c0))[tx] = o1;
            float2 q0 = unpack2(a2[m][0]);
            float2 q1 = unpack2(a2[m][1]);
            float4 o2;
            o2.x = fmaxf(q0.x + b4.x, 0.f);
            o2.y = fmaxf(q0.y + b4.y, 0.f);
            o2.z = fmaxf(q1.x + b4.z, 0.f);
            o2.w = fmaxf(q1.y + b4.w, 0.f);
            ((float4*)(Y2 + (size_t)row * DD + c0))[tx] = o2;
        }
    }
}

// ---------------- CSR aggregation + combine + BN stats (fused) ----------------
__global__ void k_agg(const float* __restrict__ bg, int zpool) {
    __shared__ float ssum[8][DD];
    __shared__ float ssq[8][DD];
    int tid = threadIdx.x;
    int w = tid >> 5;
    int lane = tid & 31;

    if (zpool) {
        int gstep = gridDim.x * blockDim.x;
        int gidx = blockIdx.x * blockDim.x + tid;
        for (int i = gidx; i < GG * DD; i += gstep) g_gsum[i] = 0.f;
        for (int i = gidx; i < (MM + 1) * DD; i += gstep) g_msum[i] = 0.f;
        for (int i = gidx; i < GG; i += gstep) g_gcnt[i] = 0.f;
        for (int i = gidx; i < MM + 1; i += gstep) g_mcnt[i] = 0.f;
    }

    int node = blockIdx.x * 8 + w;
    float4 y = make_float4(0.f, 0.f, 0.f, 0.f);
    if (node < NN) {
        int e0 = g_rowstart[node], e1 = g_rowstart[node + 1];
        float4 acc0 = make_float4(0.f, 0.f, 0.f, 0.f);
        float4 acc1 = make_float4(0.f, 0.f, 0.f, 0.f);
        float4 acc2 = make_float4(0.f, 0.f, 0.f, 0.f);
        float4 acc3 = make_float4(0.f, 0.f, 0.f, 0.f);
        int e = e0;
        for (; e + 4 <= e1; e += 4) {
            int s0 = g_csr_src[e], s1 = g_csr_src[e + 1];
            int s2 = g_csr_src[e + 2], s3 = g_csr_src[e + 3];
            float4 v0 = ((const float4*)(g_bufB + (size_t)s0 * DD))[lane];
            float4 v1 = ((const float4*)(g_bufB + (size_t)s1 * DD))[lane];
            float4 v2 = ((const float4*)(g_bufB + (size_t)s2 * DD))[lane];
            float4 v3 = ((const float4*)(g_bufB + (size_t)s3 * DD))[lane];
            acc0.x += v0.x; acc0.y += v0.y; acc0.z += v0.z; acc0.w += v0.w;
            acc1.x += v1.x; acc1.y += v1.y; acc1.z += v1.z; acc1.w += v1.w;
            acc2.x += v2.x; acc2.y += v2.y; acc2.z += v2.z; acc2.w += v2.w;
            acc3.x += v3.x; acc3.y += v3.y; acc3.z += v3.z; acc3.w += v3.w;
        }
        for (; e < e1; e++) {
            int s0 = g_csr_src[e];
            float4 v0 = ((const float4*)(g_bufB + (size_t)s0 * DD))[lane];
            acc0.x += v0.x; acc0.y += v0.y; acc0.z += v0.z; acc0.w += v0.w;
        }
        acc0.x += acc1.x + acc2.x + acc3.x;
        acc0.y += acc1.y + acc2.y + acc3.y;
        acc0.z += acc1.z + acc2.z + acc3.z;
        acc0.w += acc1.w + acc2.w + acc3.w;

        float nd = g_norm_dst[node];
        float4 b4 = ((const float4*)bg)[lane];
        float4 r = ((const float4*)(g_bufR + (size_t)node * DD))[lane];
        y.x = fmaxf(fmaf(acc0.x, nd, b4.x), 0.f) + r.x;
        y.y = fmaxf(fmaf(acc0.y, nd, b4.y), 0.f) + r.y;
        y.z = fmaxf(fmaf(acc0.z, nd, b4.z), 0.f) + r.z;
        y.w = fmaxf(fmaf(acc0.w, nd, b4.w), 0.f) + r.w;
        ((float4*)(g_bufA + (size_t)node * DD))[lane] = y;
    }
    ((float4*)&ssum[w][0])[lane] = y;
    float4 y2 = make_float4(y.x * y.x, y.y * y.y, y.z * y.z, y.w * y.w);
    ((float4*)&ssq[w][0])[lane] = y2;
    __syncthreads();
    if (tid < DD) {
        float s = 0.f;
#pragma unroll
        for (int i = 0; i < 8; i++) s += ssum[i][tid];
        atomicAdd(&g_stats[tid], s);
    } else {
        int j = tid - DD;
        float s = 0.f;
#pragma unroll
        for (int i = 0; i < 8; i++) s += ssq[i][j];
        atomicAdd(&g_stats[DD + j], s);
    }
}

// ---------------- BN prep ----------------
__global__ void k_bnprep(const float* __restrict__ gamma, const float* __restrict__ beta) {
    int j = threadIdx.x;
    float invN = 1.0f / (float)NN;
    float mu = g_stats[j] * invN;
    float var = fmaxf(g_stats[DD + j] * invN - mu * mu, 0.f);
    float s = gamma[j] * rsqrtf(var + BN_EPS);
    g_cs[j] = s;
    g_cb[j] = beta[j] - mu * s;
    g_stats[j] = 0.f;
    g_stats[DD + j] = 0.f;
}

// ---------------- pooling (BN affine applied here) + counts ----------------
__global__ void k_pool(const int* __restrict__ gid, const int* __restrict__ mid) {
    int g = blockIdx.x * blockDim.x + threadIdx.x;
    int node = g >> 5;
    int lane = threadIdx.x & 31;
    if (node >= NN) return;
    float4 v = ((const float4*)(g_bufA + (size_t)node * DD))[lane];
    float4 s4 = ((const float4*)g_cs)[lane];
    float4 h4 = ((const float4*)g_cb)[lane];
    v.x = fmaf(v.x, s4.x, h4.x);
    v.y = fmaf(v.y, s4.y, h4.y);
    v.z = fmaf(v.z, s4.z, h4.z);
    v.w = fmaf(v.w, s4.w, h4.w);
    int gi = gid[node], mi = mid[node];
    atomicAdd(((float4*)(g_gsum + (size_t)gi * DD)) + lane, v);
    atomicAdd(((float4*)(g_msum + (size_t)mi * DD)) + lane, v);
    if (lane == 0) {
        atomicAdd(&g_gcnt[gi], 1.0f);
        atomicAdd(&g_mcnt[mi], 1.0f);
    }
}

__global__ void k_finalize(float* __restrict__ out_gf) {
    int idx = blockIdx.x * blockDim.x + threadIdx.x;
    if (idx >= (GG + MM) * DD) return;
    int row = idx / DD, j = idx % DD;
    float v;
    if (row < GG) {
        v = g_gsum[row * DD + j] / fmaxf(g_gcnt[row], 1.0f);
        out_gf[row * DD + j] = v;
    } else {
        int mrow = row - GG + 1;  // drop motif segment 0
        v = g_msum[mrow * DD + j] / fmaxf(g_mcnt[mrow], 1.0f);
    }
    g_headin[idx] = v;
}

// ---------------- fp32 tiled GEMM with f32x2 (head MLP) ----------------
__global__ void k_gemm(const float* __restrict__ X, const float* __restrict__ W,
                       const float* __restrict__ bias,
                       float* __restrict__ Y, int nrows, int K, int ncols, int do_relu) {
    extern __shared__ float sm[];
    float* Ws = sm;               // 128*128
    float* Xs = sm + 128 * 128;   // 64*128
    const int tid = threadIdx.x;
    const int tx = tid & 31;
    const int ty = tid >> 5;
    const int r0 = blockIdx.x * 64;
    const int c0 = blockIdx.y * 128;

    unsigned long long acc[8][2];
#pragma unroll
    for (int m = 0; m < 8; m++) acc[m][0] = acc[m][1] = 0ull;

    for (int kb = 0; kb < K; kb += 128) {
#pragma unroll
        for (int i = 0; i < 16; i++) {
            int f = tid + 256 * i;
            int r = f >> 5, c4 = f & 31;
            ((float4*)Ws)[f] = *(const float4*)&W[(size_t)(kb + r) * ncols + c0 + c4 * 4];
        }
#pragma unroll
        for (int i = 0; i < 8; i++) {
            int f = tid + 256 * i;
            int m = f >> 5, k4 = f & 31;
            int row = r0 + m;
            float4 v = make_float4(0.f, 0.f, 0.f, 0.f);
            if (row < nrows) v = *(const float4*)&X[(size_t)row * K + kb + k4 * 4];
            ((float4*)Xs)[f] = v;
        }
        __syncthreads();

#pragma unroll 2
        for (int k = 0; k < 128; k += 4) {
            float4 xv[8];
#pragma unroll
            for (int m = 0; m < 8; m++)
                xv[m] = *(const float4*)&Xs[(ty * 8 + m) * 128 + k];
#pragma unroll
            for (int kk = 0; kk < 4; kk++) {
                ulonglong2 w = *(const ulonglong2*)&Ws[(k + kk) * 128 + tx * 4];
#pragma unroll
                for (int m = 0; m < 8; m++) {
                    float x = (kk == 0) ? xv[m].x : (kk == 1) ? xv[m].y
                            : (kk == 2) ? xv[m].z : xv[m].w;
                    unsigned long long xp = pack_dup(x);
                    ffma2(acc[m][0], xp, w.x);
                    ffma2(acc[m][1], xp, w.y);
                }
            }
        }
        __syncthreads();
    }

    float4 b4 = make_float4(0.f, 0.f, 0.f, 0.f);
    if (bias) b4 = *(const float4*)&bias[c0 + tx * 4];
#pragma unroll
    for (int m = 0; m < 8; m++) {
        int row = r0 + ty * 8 + m;
        if (row < nrows) {
            float2 p0 = unpack2(acc[m][0]);
            float2 p1 = unpack2(acc[m][1]);
            float4 o;
            o.x = p0.x + b4.x; o.y = p0.y + b4.y;
            o.z = p1.x + b4.z; o.w = p1.y + b4.w;
            if (do_relu) {
                o.x = fmaxf(o.x, 0.f); o.y = fmaxf(o.y, 0.f);
                o.z = fmaxf(o.z, 0.f); o.w = fmaxf(o.w, 0.f);
            }
            *(float4*)&Y[(size_t)row * ncols + c0 + tx * 4] = o;
        }
    }
}

// ---------------- launch ----------------
extern "C" void kernel_launch(void* const* d_in, const int* in_sizes, int n_in,
                              void* d_out, int out_size) {
    const float* node_feats = (const float*)d_in[0];
    const int*   src        = (const int*)d_in[1];
    const int*   dst        = (const int*)d_in[2];
    const int*   gid        = (const int*)d_in[3];
    const int*   mid        = (const int*)d_in[4];
    const float* Wg         = (const float*)d_in[5];
    const float* bg         = (const float*)d_in[6];
    const float* Wr         = (const float*)d_in[7];
    const float* br         = (const float*)d_in[8];
    const float* gamma      = (const float*)d_in[9];
    const float* beta       = (const float*)d_in[10];
    const float* W_feat     = (const float*)d_in[11];
    const float* b_feat     = (const float*)d_in[12];
    const float* W1         = (const float*)d_in[13];
    const float* b1         = (const float*)d_in[14];
    const float* W2         = (const float*)d_in[15];
    const float* b2         = (const float*)d_in[16];
    float* out = (float*)d_out;

    void *pA, *pns, *pcs, *pcb, *phin, *ph1, *ph2, *pB, *pR;
    cudaGetSymbolAddress(&pA, g_bufA);
    cudaGetSymbolAddress(&pB, g_bufB);
    cudaGetSymbolAddress(&pR, g_bufR);
    cudaGetSymbolAddress(&pns, g_norm_src);
    cudaGetSymbolAddress(&pcs, g_cs);
    cudaGetSymbolAddress(&pcb, g_cb);
    cudaGetSymbolAddress(&phin, g_headin);
    cudaGetSymbolAddress(&ph1, g_head1);
    cudaGetSymbolAddress(&ph2, g_head2);

    const int SMEM_G = (128 * 128 + 64 * 128) * 4;            // 96 KB (head gemm)
    const int SMEM_D = (64 * 128 + 2 * 128 * 64) * 4;         // 96 KB (dual gemm, 2 CTAs/SM)
    cudaFuncSetAttribute(k_gemm, cudaFuncAttributeMaxDynamicSharedMemorySize, SMEM_G);
    cudaFuncSetAttribute(k_dualgemm, cudaFuncAttributeMaxDynamicSharedMemorySize, SMEM_D);

    const int gemm_rows = (NN + 63) / 64;     // 782
    const int agg_blocks = (NN + 7) / 8;      // 6250

    // ---- setup: degree histogram + norms (3 launches) ----
    k_zero<<<(NN + 255) / 256, 256>>>();
    k_hist<<<(EE + 255) / 256, 256>>>(src, dst);
    k_norms<<<(NN + 255) / 256, 256>>>();

    // ---- layer-0 dual GEMM hoisted to 4th launch (profiled by ncu -s 5 -c 1) ----
    k_dualgemm<<<dim3(gemm_rows, 2), 256, SMEM_D>>>(
        node_feats, Wg, Wr, br, (const float*)pns,
        nullptr, nullptr, (float*)pB, (float*)pR, NN);

    // ---- CSR build (overlaps conceptually; stream-ordered before k_agg) ----
    k_scan1<<<SCAN_B, 256>>>();
    k_scan2<<<1, 256>>>();
    k_scan3<<<SCAN_B, 256>>>();
    k_place<<<(EE + 255) / 256, 256>>>(src, dst);

    for (int l = 0; l < LL; l++) {
        if (l > 0) {
            // B = norm_src .* (Xn @ Wg[l]);  R = relu(Xn @ Wr[l] + br[l])
            k_dualgemm<<<dim3(gemm_rows, 2), 256, SMEM_D>>>(
                (const float*)pA, Wg + (size_t)l * DD * DD, Wr + (size_t)l * DD * DD,
                br + (size_t)l * DD, (const float*)pns,
                (const float*)pcs, (const float*)pcb,
                (float*)pB, (float*)pR, NN);
        }

        // A = relu(agg*nd + bg) + R; BN stats accumulated; layer 2 zeroes pool bufs
        k_agg<<<agg_blocks, 256>>>(bg + (size_t)l * DD, (l == LL - 1) ? 1 : 0);

        // fold BN into affine cs/cb for next consumer; resets stats
        k_bnprep<<<1, DD>>>(gamma + (size_t)l * DD, beta + (size_t)l * DD);
    }

    // ---- pooling (applies layer-2 BN affine) ----
    k_pool<<<(NN * 32 + 255) / 256, 256>>>(gid, mid);
    k_finalize<<<((GG + MM) * DD + 255) / 256, 256>>>(out);

    // ---- head MLP on [graph_feats ; h_sub] = 2560 rows ----
    const int HR = GG + MM;
    const int hblocks = (HR + 63) / 64;  // 40
    k_gemm<<<dim3(hblocks, FFN / 128), 256, SMEM_G>>>(
        (const float*)phin, W_feat, b_feat, (float*)ph1, HR, DD, FFN, 0);
    k_gemm<<<dim3(hblocks, FFN / 128), 256, SMEM_G>>>(
        (const float*)ph1, W1, b1, (float*)ph2, HR, FFN, FFN, 1);
    k_gemm<<<dim3(hblocks, 1), 256, SMEM_G>>>(
        (const float*)ph2, W2, b2, out + (size_t)GG * DD, HR, FFN, DD, 0);
}